// round 1
// baseline (speedup 1.0000x reference)
#include <cuda_runtime.h>
#include <cstdint>

#define N      2048
#define DM     512
#define HH     8
#define DIMH   64
#define NN     (N * N)

// ---------------- device scratch (static, allocation-free) ----------------
__device__ float    g_q[DM * N];
__device__ float    g_k[DM * N];
__device__ float    g_v[DM * N];
__device__ float    g_x[DM * N];
__device__ float    g_S[HH * NN];   // raw scores (pre-mask), scaled by 1/8
__device__ float    g_P[HH * NN];   // softmax probabilities
__device__ unsigned g_smin_enc;     // order-preserving encoded global min
__device__ unsigned g_mask_or;      // mask dtype fingerprint

// order-preserving float <-> uint encoding (min over uint == min over float)
__device__ __forceinline__ unsigned enc_f(float x) {
    unsigned u = __float_as_uint(x);
    return (u & 0x80000000u) ? ~u : (u | 0x80000000u);
}
__device__ __forceinline__ float dec_f(unsigned u) {
    return (u & 0x80000000u) ? __uint_as_float(u & 0x7FFFFFFFu)
                             : __uint_as_float(~u);
}

// mask accessor: returns 1.0f where mask is FALSE (i.e. the (~mask) factor)
__device__ __forceinline__ float mask_not(const void* mask, int i) {
    unsigned o = g_mask_or;
    bool mv;
    if (o == 0x3F800000u)      mv = ((const float*)mask)[i] != 0.0f;  // f32 0/1
    else if (o == 1u)          mv = ((const int*)mask)[i] != 0;       // i32 0/1
    else                       mv = ((const unsigned char*)mask)[i] != 0; // u8
    return mv ? 0.0f : 1.0f;
}

// ---------------- kernels ----------------

__global__ void init_kernel() {
    g_smin_enc = 0xFFFFFFFFu;   // +max in encoded order
    g_mask_or  = 0u;
}

// Scan first 4MB of the mask buffer (safe under every candidate dtype) and OR
// all 32-bit words. i32 0/1 -> OR == 0x1 ; f32 0/1 -> OR == 0x3F800000 ;
// u8 bool -> OR ~ 0x01010101 (any other value).
__global__ void mask_detect_kernel(const unsigned* __restrict__ m) {
    __shared__ unsigned sh[256];
    unsigned acc = 0;
    const int total = NN / 4;  // 1M words = 4MB
    for (int i = blockIdx.x * blockDim.x + threadIdx.x; i < total;
         i += gridDim.x * blockDim.x)
        acc |= m[i];
    sh[threadIdx.x] = acc;
    __syncthreads();
    for (int s = 128; s > 0; s >>= 1) {
        if (threadIdx.x < s) sh[threadIdx.x] |= sh[threadIdx.x + s];
        __syncthreads();
    }
    if (threadIdx.x == 0) atomicOr(&g_mask_or, sh[0]);
}

// C[64o x 64n tile] = W(512x512) @ X(512x2048) + b.  256 thr, 4x4 per thread.
__global__ void proj_kernel(const float* __restrict__ W,
                            const float* __restrict__ X,
                            const float* __restrict__ b,
                            float* __restrict__ C) {
    __shared__ float Ws[32][65];   // [c][o], padded (conflict-free col writes)
    __shared__ float Xs[32][64];   // [c][n], rows 16B-aligned for float4
    const int tid = threadIdx.x;
    const int n0 = blockIdx.x * 64, o0 = blockIdx.y * 64;
    const int ty = tid >> 4, tx = tid & 15;
    float acc[4][4] = {};
    for (int c0 = 0; c0 < DM; c0 += 32) {
        #pragma unroll
        for (int i = tid; i < 64 * 32; i += 256) {
            int o = i >> 5, c = i & 31;
            Ws[c][o] = W[(o0 + o) * DM + c0 + c];
        }
        #pragma unroll
        for (int i = tid; i < 32 * 64; i += 256) {
            int c = i >> 6, n = i & 63;
            Xs[c][n] = X[(c0 + c) * N + n0 + n];
        }
        __syncthreads();
        #pragma unroll
        for (int kk = 0; kk < 32; kk++) {
            float a0 = Ws[kk][ty * 4 + 0], a1 = Ws[kk][ty * 4 + 1];
            float a2 = Ws[kk][ty * 4 + 2], a3 = Ws[kk][ty * 4 + 3];
            float4 bb = *(const float4*)&Xs[kk][tx * 4];
            acc[0][0] += a0 * bb.x; acc[0][1] += a0 * bb.y;
            acc[0][2] += a0 * bb.z; acc[0][3] += a0 * bb.w;
            acc[1][0] += a1 * bb.x; acc[1][1] += a1 * bb.y;
            acc[1][2] += a1 * bb.z; acc[1][3] += a1 * bb.w;
            acc[2][0] += a2 * bb.x; acc[2][1] += a2 * bb.y;
            acc[2][2] += a2 * bb.z; acc[2][3] += a2 * bb.w;
            acc[3][0] += a3 * bb.x; acc[3][1] += a3 * bb.y;
            acc[3][2] += a3 * bb.z; acc[3][3] += a3 * bb.w;
        }
        __syncthreads();
    }
    #pragma unroll
    for (int i = 0; i < 4; i++) {
        float bias = b[o0 + ty * 4 + i];
        #pragma unroll
        for (int j = 0; j < 4; j++)
            C[(o0 + ty * 4 + i) * N + n0 + tx * 4 + j] = acc[i][j] + bias;
    }
}

// S[h][n][m] = (1/8) * sum_d q[(d*8+h)][n] * k[(d*8+h)][m], plus global min.
__global__ void scores_kernel(const float* __restrict__ q,
                              const float* __restrict__ k,
                              float* __restrict__ S) {
    __shared__ float qs[64][64];   // [d][n] rows aligned for float4
    __shared__ float ks[64][64];   // [d][m]
    __shared__ float red[256];
    const int tid = threadIdx.x;
    const int h = blockIdx.z;
    const int m0 = blockIdx.x * 64, n0 = blockIdx.y * 64;
    const int ty = tid >> 4, tx = tid & 15;
    #pragma unroll
    for (int i = tid; i < 4096; i += 256) {
        int d = i >> 6, c = i & 63;
        qs[d][c] = q[(d * HH + h) * N + n0 + c];
        ks[d][c] = k[(d * HH + h) * N + m0 + c];
    }
    __syncthreads();
    float acc[4][4] = {};
    #pragma unroll
    for (int d = 0; d < 64; d++) {
        float4 av = *(const float4*)&qs[d][ty * 4];
        float4 bv = *(const float4*)&ks[d][tx * 4];
        float a[4] = {av.x, av.y, av.z, av.w};
        float b[4] = {bv.x, bv.y, bv.z, bv.w};
        #pragma unroll
        for (int i = 0; i < 4; i++)
            #pragma unroll
            for (int j = 0; j < 4; j++)
                acc[i][j] += a[i] * b[j];
    }
    float lmin = 3.0e38f;
    float* base = S + h * NN;
    #pragma unroll
    for (int i = 0; i < 4; i++)
        #pragma unroll
        for (int j = 0; j < 4; j++) {
            float v = acc[i][j] * 0.125f;
            base[(n0 + ty * 4 + i) * N + m0 + tx * 4 + j] = v;
            lmin = fminf(lmin, v);
        }
    red[tid] = lmin;
    __syncthreads();
    for (int s = 128; s > 0; s >>= 1) {
        if (tid < s) red[tid] = fminf(red[tid], red[tid + s]);
        __syncthreads();
    }
    if (tid == 0) atomicMin(&g_smin_enc, enc_f(red[0]));
}

// out2[n][m] = mean_h(S) + smin * (~mask)   (second return value)
__global__ void mean_kernel(const float* __restrict__ S,
                            const void* __restrict__ mask,
                            float* __restrict__ out2) {
    int idx = blockIdx.x * 256 + threadIdx.x;
    float smin = dec_f(g_smin_enc);
    float s = 0.0f;
    #pragma unroll
    for (int h = 0; h < HH; h++) s += S[h * NN + idx];
    out2[idx] = s * 0.125f + smin * mask_not(mask, idx);
}

// row softmax over m (one block per (h,n) row), with additive smin*(~mask)
__global__ void softmax_kernel(const float* __restrict__ S,
                               const void* __restrict__ mask,
                               float* __restrict__ P) {
    const int n = blockIdx.x, h = blockIdx.y, tid = threadIdx.x;
    const float smin = dec_f(g_smin_enc);
    const float* row = S + h * NN + n * N;
    const int moff = n * N;
    __shared__ float sh[8];
    float vals[8];
    float mx = -3.0e38f;
    #pragma unroll
    for (int j = 0; j < 8; j++) {
        int m = j * 256 + tid;
        float v = row[m] + smin * mask_not(mask, moff + m);
        vals[j] = v;
        mx = fmaxf(mx, v);
    }
    #pragma unroll
    for (int o = 16; o > 0; o >>= 1) mx = fmaxf(mx, __shfl_xor_sync(~0u, mx, o));
    if ((tid & 31) == 0) sh[tid >> 5] = mx;
    __syncthreads();
    if (tid == 0) {
        float t = sh[0];
        #pragma unroll
        for (int w = 1; w < 8; w++) t = fmaxf(t, sh[w]);
        sh[0] = t;
    }
    __syncthreads();
    const float MX = sh[0];
    __syncthreads();
    float sum = 0.0f;
    #pragma unroll
    for (int j = 0; j < 8; j++) {
        float e = __expf(vals[j] - MX);
        vals[j] = e;
        sum += e;
    }
    #pragma unroll
    for (int o = 16; o > 0; o >>= 1) sum += __shfl_xor_sync(~0u, sum, o);
    if ((tid & 31) == 0) sh[tid >> 5] = sum;
    __syncthreads();
    if (tid == 0) {
        float t = 0.0f;
        #pragma unroll
        for (int w = 0; w < 8; w++) t += sh[w];
        sh[0] = t;
    }
    __syncthreads();
    const float inv = 1.0f / sh[0];
    float* prow = P + h * NN + n * N;
    #pragma unroll
    for (int j = 0; j < 8; j++) prow[j * 256 + tid] = vals[j] * inv;
}

// x[(d*8+h)][n] = sum_m P[h][n][m] * v[(d*8+h)][m]
__global__ void pv_kernel(const float* __restrict__ P,
                          const float* __restrict__ v,
                          float* __restrict__ x) {
    __shared__ float ps[64][65];   // [n][m]
    __shared__ float vs[64][65];   // [d][m]
    const int tid = threadIdx.x;
    const int h = blockIdx.y;
    const int n0 = blockIdx.x * 64;
    const int ty = tid >> 4, tx = tid & 15;
    float acc[4][4] = {};          // [d-sub][n-sub]
    for (int m0 = 0; m0 < N; m0 += 64) {
        #pragma unroll
        for (int i = tid; i < 4096; i += 256) {
            int r = i >> 6, c = i & 63;
            ps[r][c] = P[h * NN + (n0 + r) * N + m0 + c];
            vs[r][c] = v[(r * HH + h) * N + m0 + c];
        }
        __syncthreads();
        #pragma unroll
        for (int m = 0; m < 64; m++) {
            float a0 = vs[ty * 4 + 0][m], a1 = vs[ty * 4 + 1][m];
            float a2 = vs[ty * 4 + 2][m], a3 = vs[ty * 4 + 3][m];
            float b0 = ps[tx * 4 + 0][m], b1 = ps[tx * 4 + 1][m];
            float b2 = ps[tx * 4 + 2][m], b3 = ps[tx * 4 + 3][m];
            acc[0][0] += a0 * b0; acc[0][1] += a0 * b1;
            acc[0][2] += a0 * b2; acc[0][3] += a0 * b3;
            acc[1][0] += a1 * b0; acc[1][1] += a1 * b1;
            acc[1][2] += a1 * b2; acc[1][3] += a1 * b3;
            acc[2][0] += a2 * b0; acc[2][1] += a2 * b1;
            acc[2][2] += a2 * b2; acc[2][3] += a2 * b3;
            acc[3][0] += a3 * b0; acc[3][1] += a3 * b1;
            acc[3][2] += a3 * b2; acc[3][3] += a3 * b3;
        }
        __syncthreads();
    }
    #pragma unroll
    for (int i = 0; i < 4; i++) {
        int d = ty * 4 + i;
        #pragma unroll
        for (int j = 0; j < 4; j++)
            x[(d * HH + h) * N + n0 + tx * 4 + j] = acc[i][j];
    }
}

// ---------------- launch ----------------
extern "C" void kernel_launch(void* const* d_in, const int* in_sizes, int n_in,
                              void* d_out, int out_size) {
    const float* query = (const float*)d_in[0];
    const float* key   = (const float*)d_in[1];
    const float* value = (const float*)d_in[2];
    // d_in[3] = dist (unused by the model)
    const void*  mask  = d_in[4];
    const float* Wq = (const float*)d_in[5];
    const float* bq = (const float*)d_in[6];
    const float* Wk = (const float*)d_in[7];
    const float* bk = (const float*)d_in[8];
    const float* Wv = (const float*)d_in[9];
    const float* bv = (const float*)d_in[10];
    const float* Wm = (const float*)d_in[11];
    const float* bm = (const float*)d_in[12];
    float* out = (float*)d_out;

    float *qp, *kp, *vp, *xp, *Sp, *Pp;
    cudaGetSymbolAddress((void**)&qp, g_q);
    cudaGetSymbolAddress((void**)&kp, g_k);
    cudaGetSymbolAddress((void**)&vp, g_v);
    cudaGetSymbolAddress((void**)&xp, g_x);
    cudaGetSymbolAddress((void**)&Sp, g_S);
    cudaGetSymbolAddress((void**)&Pp, g_P);

    init_kernel<<<1, 1>>>();
    mask_detect_kernel<<<64, 256>>>((const unsigned*)mask);

    dim3 gproj(N / 64, DM / 64);
    proj_kernel<<<gproj, 256>>>(Wq, query, bq, qp);
    proj_kernel<<<gproj, 256>>>(Wk, key, bk, kp);
    proj_kernel<<<gproj, 256>>>(Wv, value, bv, vp);

    dim3 gs(N / 64, N / 64, HH);
    scores_kernel<<<gs, 256>>>(qp, kp, Sp);

    mean_kernel<<<NN / 256, 256>>>(Sp, mask, out + DM * N);
    softmax_kernel<<<dim3(N, HH), 256>>>(Sp, mask, Pp);

    pv_kernel<<<dim3(N / 64, HH), 256>>>(Pp, vp, xp);
    proj_kernel<<<gproj, 256>>>(Wm, xp, bm, out);
}

// round 2
// speedup vs baseline: 1.6809x; 1.6809x over previous
#include <cuda_runtime.h>

#define N      2048
#define DM     512
#define HH     8
#define NN     (N * N)

typedef unsigned long long ull;

// ---------------- device scratch (static, allocation-free) ----------------
__device__ float    g_q[DM * N];
__device__ float    g_k[DM * N];
__device__ float    g_v[DM * N];
__device__ float    g_x1[DM * N];   // PV partial (m in [0,1024))
__device__ float    g_x2[DM * N];   // PV partial (m in [1024,2048))
__device__ float    g_S[HH * NN];   // raw scores, scaled by 1/8
__device__ float    g_rmax[HH * N]; // per-(h,n) row max of masked scores
__device__ float    g_rinv[HH * N]; // per-(h,n) 1/sum(exp)
__device__ unsigned g_smin_enc;
__device__ unsigned g_mask_or;

// ---------------- helpers ----------------
__device__ __forceinline__ unsigned enc_f(float x) {
    unsigned u = __float_as_uint(x);
    return (u & 0x80000000u) ? ~u : (u | 0x80000000u);
}
__device__ __forceinline__ float dec_f(unsigned u) {
    return (u & 0x80000000u) ? __uint_as_float(u & 0x7FFFFFFFu)
                             : __uint_as_float(~u);
}
__device__ __forceinline__ float mask_not(const void* mask, int i) {
    unsigned o = g_mask_or;
    bool mv;
    if (o == 0x3F800000u)      mv = ((const float*)mask)[i] != 0.0f;
    else if (o == 1u)          mv = ((const int*)mask)[i] != 0;
    else                       mv = ((const unsigned char*)mask)[i] != 0;
    return mv ? 0.0f : 1.0f;
}
__device__ __forceinline__ float4 mask_not4(const void* mask, int i) {
    unsigned o = g_mask_or;
    float4 r;
    if (o == 0x3F800000u) {
        float4 m = *(const float4*)((const float*)mask + i);
        r.x = m.x != 0.0f ? 0.f : 1.f; r.y = m.y != 0.0f ? 0.f : 1.f;
        r.z = m.z != 0.0f ? 0.f : 1.f; r.w = m.w != 0.0f ? 0.f : 1.f;
    } else if (o == 1u) {
        int4 m = *(const int4*)((const int*)mask + i);
        r.x = m.x ? 0.f : 1.f; r.y = m.y ? 0.f : 1.f;
        r.z = m.z ? 0.f : 1.f; r.w = m.w ? 0.f : 1.f;
    } else {
        uchar4 m = *(const uchar4*)((const unsigned char*)mask + i);
        r.x = m.x ? 0.f : 1.f; r.y = m.y ? 0.f : 1.f;
        r.z = m.z ? 0.f : 1.f; r.w = m.w ? 0.f : 1.f;
    }
    return r;
}

// packed fp32x2 FMA (Blackwell dual-rate fp32 path; ptxas never emits it from C++)
__device__ __forceinline__ void ffma2(ull& d, ull a, ull b) {
    asm("fma.rn.f32x2 %0, %1, %2, %0;" : "+l"(d) : "l"(a), "l"(b));
}
__device__ __forceinline__ ull pk2(float x, float y) {
    ull r; asm("mov.b64 %0, {%1, %2};" : "=l"(r) : "f"(x), "f"(y)); return r;
}
__device__ __forceinline__ float2 up2(ull p) {
    float2 r; asm("mov.b64 {%0, %1}, %2;" : "=f"(r.x), "=f"(r.y) : "l"(p)); return r;
}

// 16-deep K-slab of a 64(M)x128(N) tile: 128 threads, 8x8 per thread.
// N-fragment is split into two 64-wide halves (cols tx*4 and 64+tx*4)
// so LDS.128 reads are bank-conflict-free.
__device__ __forceinline__ void gemm16(const float (*__restrict__ As)[64],
                                       const float (*__restrict__ Bs)[132],
                                       ull acc[8][4], int tx, int ty) {
    #pragma unroll
    for (int k = 0; k < 16; k++) {
        float4 a0 = *(const float4*)&As[k][ty * 8];
        float4 a1 = *(const float4*)&As[k][ty * 8 + 4];
        float4 b0 = *(const float4*)&Bs[k][tx * 4];
        float4 b1 = *(const float4*)&Bs[k][64 + tx * 4];
        ull pb0 = pk2(b0.x, b0.y), pb1 = pk2(b0.z, b0.w);
        ull pb2 = pk2(b1.x, b1.y), pb3 = pk2(b1.z, b1.w);
        float av[8] = {a0.x, a0.y, a0.z, a0.w, a1.x, a1.y, a1.z, a1.w};
        #pragma unroll
        for (int i = 0; i < 8; i++) {
            ull pa = pk2(av[i], av[i]);
            ffma2(acc[i][0], pa, pb0);
            ffma2(acc[i][1], pa, pb1);
            ffma2(acc[i][2], pa, pb2);
            ffma2(acc[i][3], pa, pb3);
        }
    }
}

// ---------------- kernels ----------------

__global__ void init_kernel() {
    g_smin_enc = 0xFFFFFFFFu;
    g_mask_or  = 0u;
}

__global__ void mask_detect_kernel(const unsigned* __restrict__ m) {
    __shared__ unsigned sh[256];
    unsigned acc = 0;
    const int total = NN / 4;
    for (int i = blockIdx.x * blockDim.x + threadIdx.x; i < total;
         i += gridDim.x * blockDim.x)
        acc |= m[i];
    sh[threadIdx.x] = acc;
    __syncthreads();
    for (int s = 128; s > 0; s >>= 1) {
        if (threadIdx.x < s) sh[threadIdx.x] |= sh[threadIdx.x + s];
        __syncthreads();
    }
    if (threadIdx.x == 0) atomicOr(&g_mask_or, sh[0]);
}

// Fused q/k/v projections: z picks which. C[64 x 128 tile] = W @ X + b.
__global__ __launch_bounds__(128) void qkv_kernel(
    const float* __restrict__ Wq, const float* __restrict__ Wk,
    const float* __restrict__ Wv, const float* __restrict__ bq,
    const float* __restrict__ bk, const float* __restrict__ bv,
    const float* __restrict__ Xq, const float* __restrict__ Xk,
    const float* __restrict__ Xv,
    float* __restrict__ Oq, float* __restrict__ Ok, float* __restrict__ Ov)
{
    const float *W, *Bv_, *X;
    float* O;
    if (blockIdx.z == 0)      { W = Wq; Bv_ = bq; X = Xq; O = Oq; }
    else if (blockIdx.z == 1) { W = Wk; Bv_ = bk; X = Xk; O = Ok; }
    else                      { W = Wv; Bv_ = bv; X = Xv; O = Ov; }

    __shared__ float As[2][16][64];
    __shared__ float Bs[2][16][132];
    const int tid = threadIdx.x, tx = tid & 15, ty = tid >> 4;
    const int n0 = blockIdx.x * 128, m0 = blockIdx.y * 64;

    ull acc[8][4];
    #pragma unroll
    for (int i = 0; i < 8; i++)
        #pragma unroll
        for (int j = 0; j < 4; j++) acc[i][j] = 0ull;

    const int ao = tid >> 1, ac = (tid & 1) * 8;
    const float* Ap = W + (m0 + ao) * DM + ac;
    const int brow = tid >> 5, bc4 = tid & 31;
    const float* Bp = X + brow * N + n0 + bc4 * 4;

    float4 ra0, ra1, rb[4];
    ra0 = *(const float4*)(Ap);
    ra1 = *(const float4*)(Ap + 4);
    #pragma unroll
    for (int i = 0; i < 4; i++)
        rb[i] = *(const float4*)(Bp + (i * 4) * N);
    {
        As[0][ac + 0][ao] = ra0.x; As[0][ac + 1][ao] = ra0.y;
        As[0][ac + 2][ao] = ra0.z; As[0][ac + 3][ao] = ra0.w;
        As[0][ac + 4][ao] = ra1.x; As[0][ac + 5][ao] = ra1.y;
        As[0][ac + 6][ao] = ra1.z; As[0][ac + 7][ao] = ra1.w;
        #pragma unroll
        for (int i = 0; i < 4; i++)
            *(float4*)&Bs[0][brow + i * 4][bc4 * 4] = rb[i];
    }
    __syncthreads();

    const int KT = DM / 16;
    for (int kt = 0; kt < KT; kt++) {
        const int s = kt & 1;
        if (kt + 1 < KT) {
            const int c0 = (kt + 1) * 16;
            ra0 = *(const float4*)(Ap + c0);
            ra1 = *(const float4*)(Ap + c0 + 4);
            #pragma unroll
            for (int i = 0; i < 4; i++)
                rb[i] = *(const float4*)(Bp + (c0 + i * 4) * N);
        }
        gemm16(As[s], Bs[s], acc, tx, ty);
        if (kt + 1 < KT) {
            const int d = s ^ 1;
            As[d][ac + 0][ao] = ra0.x; As[d][ac + 1][ao] = ra0.y;
            As[d][ac + 2][ao] = ra0.z; As[d][ac + 3][ao] = ra0.w;
            As[d][ac + 4][ao] = ra1.x; As[d][ac + 5][ao] = ra1.y;
            As[d][ac + 6][ao] = ra1.z; As[d][ac + 7][ao] = ra1.w;
            #pragma unroll
            for (int i = 0; i < 4; i++)
                *(float4*)&Bs[d][brow + i * 4][bc4 * 4] = rb[i];
        }
        __syncthreads();
    }

    #pragma unroll
    for (int i = 0; i < 8; i++) {
        float bias = Bv_[m0 + ty * 8 + i];
        float2 v0 = up2(acc[i][0]), v1 = up2(acc[i][1]);
        float2 v2 = up2(acc[i][2]), v3 = up2(acc[i][3]);
        float4 o0 = {v0.x + bias, v0.y + bias, v1.x + bias, v1.y + bias};
        float4 o1 = {v2.x + bias, v2.y + bias, v3.x + bias, v3.y + bias};
        float* row = O + (m0 + ty * 8 + i) * N + n0;
        *(float4*)(row + tx * 4) = o0;
        *(float4*)(row + 64 + tx * 4) = o1;
    }
}

// S[h][n][m] tile [n=64][m=128], K = d = 64. Also global min (atomicMin).
__global__ __launch_bounds__(128) void scores_kernel(
    const float* __restrict__ q, const float* __restrict__ k,
    float* __restrict__ S)
{
    __shared__ float As[2][16][64];
    __shared__ float Bs[2][16][132];
    __shared__ float red[4];
    const int tid = threadIdx.x, tx = tid & 15, ty = tid >> 4;
    const int m0 = blockIdx.x * 128, n0 = blockIdx.y * 64;
    const int h = blockIdx.z;

    ull acc[8][4];
    #pragma unroll
    for (int i = 0; i < 8; i++)
        #pragma unroll
        for (int j = 0; j < 4; j++) acc[i][j] = 0ull;

    const int ad = tid >> 3, anq = tid & 7;       // A: 16 d rows x 64 n
    const float* Ap = q + (ad * HH + h) * N + n0 + anq * 8;
    const int brow = tid >> 5, bc4 = tid & 31;    // B: 16 d rows x 128 m
    const float* Bp = k + (brow * HH + h) * N + m0 + bc4 * 4;
    const int dstep = 16 * HH * N;                // advance 16 channels

    float4 ra0, ra1, rb[4];
    ra0 = *(const float4*)(Ap);
    ra1 = *(const float4*)(Ap + 4);
    #pragma unroll
    for (int i = 0; i < 4; i++)
        rb[i] = *(const float4*)(Bp + i * 4 * HH * N);
    {
        *(float4*)&As[0][ad][anq * 8] = ra0;
        *(float4*)&As[0][ad][anq * 8 + 4] = ra1;
        #pragma unroll
        for (int i = 0; i < 4; i++)
            *(float4*)&Bs[0][brow + i * 4][bc4 * 4] = rb[i];
    }
    __syncthreads();

    const int KT = 4;  // 64 / 16
    for (int kt = 0; kt < KT; kt++) {
        const int s = kt & 1;
        if (kt + 1 < KT) {
            const int off = (kt + 1) * dstep;
            ra0 = *(const float4*)(Ap + off);
            ra1 = *(const float4*)(Ap + off + 4);
            #pragma unroll
            for (int i = 0; i < 4; i++)
                rb[i] = *(const float4*)(Bp + off + i * 4 * HH * N);
        }
        gemm16(As[s], Bs[s], acc, tx, ty);
        if (kt + 1 < KT) {
            const int d = s ^ 1;
            *(float4*)&As[d][ad][anq * 8] = ra0;
            *(float4*)&As[d][ad][anq * 8 + 4] = ra1;
            #pragma unroll
            for (int i = 0; i < 4; i++)
                *(float4*)&Bs[d][brow + i * 4][bc4 * 4] = rb[i];
        }
        __syncthreads();
    }

    float lmin = 3.0e38f;
    float* base = S + h * NN;
    #pragma unroll
    for (int i = 0; i < 8; i++) {
        float2 v0 = up2(acc[i][0]), v1 = up2(acc[i][1]);
        float2 v2 = up2(acc[i][2]), v3 = up2(acc[i][3]);
        float4 o0 = {v0.x * 0.125f, v0.y * 0.125f, v1.x * 0.125f, v1.y * 0.125f};
        float4 o1 = {v2.x * 0.125f, v2.y * 0.125f, v3.x * 0.125f, v3.y * 0.125f};
        float* row = base + (n0 + ty * 8 + i) * N + m0;
        *(float4*)(row + tx * 4) = o0;
        *(float4*)(row + 64 + tx * 4) = o1;
        lmin = fminf(lmin, fminf(fminf(o0.x, o0.y), fminf(o0.z, o0.w)));
        lmin = fminf(lmin, fminf(fminf(o1.x, o1.y), fminf(o1.z, o1.w)));
    }
    #pragma unroll
    for (int o = 16; o > 0; o >>= 1)
        lmin = fminf(lmin, __shfl_xor_sync(~0u, lmin, o));
    if ((tid & 31) == 0) red[tid >> 5] = lmin;
    __syncthreads();
    if (tid == 0) {
        float m = fminf(fminf(red[0], red[1]), fminf(red[2], red[3]));
        atomicMin(&g_smin_enc, enc_f(m));
    }
}

// Per-n row: softmax stats for all 8 heads + head-mean output (out2).
__global__ __launch_bounds__(256) void stats_kernel(
    const float* __restrict__ S, const void* __restrict__ mask,
    float* __restrict__ out2)
{
    __shared__ float notm[N];
    __shared__ float red[8];
    const int n = blockIdx.x, tid = threadIdx.x;
    for (int j = tid; j < N; j += 256) notm[j] = mask_not(mask, n * N + j);
    __syncthreads();
    const float smin = dec_f(g_smin_enc);
    float msum[8] = {0, 0, 0, 0, 0, 0, 0, 0};
    #pragma unroll 1
    for (int h = 0; h < HH; h++) {
        const float* row = S + h * NN + n * N;
        float v[8], mx = -3.0e38f;
        #pragma unroll
        for (int i = 0; i < 8; i++) {
            int j = tid + i * 256;
            float s = row[j];
            msum[i] += s;
            float t = s + smin * notm[j];
            v[i] = t;
            mx = fmaxf(mx, t);
        }
        #pragma unroll
        for (int o = 16; o > 0; o >>= 1)
            mx = fmaxf(mx, __shfl_xor_sync(~0u, mx, o));
        if ((tid & 31) == 0) red[tid >> 5] = mx;
        __syncthreads();
        float MX = red[0];
        #pragma unroll
        for (int w = 1; w < 8; w++) MX = fmaxf(MX, red[w]);
        __syncthreads();
        float sum = 0.0f;
        #pragma unroll
        for (int i = 0; i < 8; i++) sum += __expf(v[i] - MX);
        #pragma unroll
        for (int o = 16; o > 0; o >>= 1)
            sum += __shfl_xor_sync(~0u, sum, o);
        if ((tid & 31) == 0) red[tid >> 5] = sum;
        __syncthreads();
        float SUM = 0.0f;
        #pragma unroll
        for (int w = 0; w < 8; w++) SUM += red[w];
        if (tid == 0) {
            g_rmax[h * N + n] = MX;
            g_rinv[h * N + n] = 1.0f / SUM;
        }
        __syncthreads();
    }
    #pragma unroll
    for (int i = 0; i < 8; i++) {
        int j = tid + i * 256;
        out2[n * N + j] = msum[i] * 0.125f + smin * notm[j];
    }
}

// PV with on-the-fly softmax: x[(d*8+h)][n] = sum_m P[h][n][m] v[(d*8+h)][m]
// Tile [d=64][n=128], K = m split in halves (blockIdx.y) into g_x1/g_x2.
__global__ __launch_bounds__(128) void pv_kernel(
    const float* __restrict__ S, const float* __restrict__ v,
    const void* __restrict__ mask,
    float* __restrict__ X1, float* __restrict__ X2)
{
    __shared__ float As[2][16][64];
    __shared__ float Bs[2][16][132];
    __shared__ float rm[128], ri[128];
    const int tid = threadIdx.x, tx = tid & 15, ty = tid >> 4;
    const int n0 = blockIdx.x * 128;
    const int mbase = blockIdx.y * (N / 2);
    const int h = blockIdx.z;
    float* O = blockIdx.y ? X2 : X1;

    rm[tid] = g_rmax[h * N + n0 + tid];
    ri[tid] = g_rinv[h * N + n0 + tid];
    const float smin = dec_f(g_smin_enc);

    ull acc[8][4];
    #pragma unroll
    for (int i = 0; i < 8; i++)
        #pragma unroll
        for (int j = 0; j < 4; j++) acc[i][j] = 0ull;

    const int ad = tid >> 1, am8 = (tid & 1) * 8;   // A: 64 d x 16 m (transpose)
    const float* Vp = v + (ad * HH + h) * N + mbase + am8;
    const int bn = tid >> 2, bmq = tid & 3;          // B: per thread 4 iters
    const float* Sb = S + h * NN + n0 * N + mbase;

    float4 ra0, ra1, rb[4];
    int rbn[4];
    // prefetch tile 0 (c0 = 0)
    ra0 = *(const float4*)(Vp);
    ra1 = *(const float4*)(Vp + 4);
    #pragma unroll
    for (int i = 0; i < 4; i++) {
        int idx = tid + i * 128;
        int nn = idx >> 2, mq = idx & 3;
        rbn[i] = nn;
        rb[i] = *(const float4*)(Sb + nn * N + mq * 4);
    }
    __syncthreads();  // rm/ri visible
    {
        As[0][am8 + 0][ad] = ra0.x; As[0][am8 + 1][ad] = ra0.y;
        As[0][am8 + 2][ad] = ra0.z; As[0][am8 + 3][ad] = ra0.w;
        As[0][am8 + 4][ad] = ra1.x; As[0][am8 + 5][ad] = ra1.y;
        As[0][am8 + 6][ad] = ra1.z; As[0][am8 + 7][ad] = ra1.w;
        #pragma unroll
        for (int i = 0; i < 4; i++) {
            int idx = tid + i * 128;
            int nn = idx >> 2, mq = idx & 3;
            float4 nm = mask_not4(mask, (n0 + nn) * N + mbase + mq * 4);
            float RM = rm[nn], RI = ri[nn];
            Bs[0][mq * 4 + 0][nn] = __expf(rb[i].x + smin * nm.x - RM) * RI;
            Bs[0][mq * 4 + 1][nn] = __expf(rb[i].y + smin * nm.y - RM) * RI;
            Bs[0][mq * 4 + 2][nn] = __expf(rb[i].z + smin * nm.z - RM) * RI;
            Bs[0][mq * 4 + 3][nn] = __expf(rb[i].w + smin * nm.w - RM) * RI;
        }
    }
    __syncthreads();

    const int KT = (N / 2) / 16;  // 64
    for (int kt = 0; kt < KT; kt++) {
        const int s = kt & 1;
        const int c1 = (kt + 1) * 16;
        if (kt + 1 < KT) {
            ra0 = *(const float4*)(Vp + c1);
            ra1 = *(const float4*)(Vp + c1 + 4);
            #pragma unroll
            for (int i = 0; i < 4; i++) {
                int idx = tid + i * 128;
                int nn = idx >> 2, mq = idx & 3;
                rb[i] = *(const float4*)(Sb + nn * N + c1 + mq * 4);
            }
        }
        gemm16(As[s], Bs[s], acc, tx, ty);
        if (kt + 1 < KT) {
            const int d = s ^ 1;
            As[d][am8 + 0][ad] = ra0.x; As[d][am8 + 1][ad] = ra0.y;
            As[d][am8 + 2][ad] = ra0.z; As[d][am8 + 3][ad] = ra0.w;
            As[d][am8 + 4][ad] = ra1.x; As[d][am8 + 5][ad] = ra1.y;
            As[d][am8 + 6][ad] = ra1.z; As[d][am8 + 7][ad] = ra1.w;
            #pragma unroll
            for (int i = 0; i < 4; i++) {
                int idx = tid + i * 128;
                int nn = idx >> 2, mq = idx & 3;
                float4 nm = mask_not4(mask, (n0 + nn) * N + mbase + c1 + mq * 4);
                float RM = rm[nn], RI = ri[nn];
                Bs[d][mq * 4 + 0][nn] = __expf(rb[i].x + smin * nm.x - RM) * RI;
                Bs[d][mq * 4 + 1][nn] = __expf(rb[i].y + smin * nm.y - RM) * RI;
                Bs[d][mq * 4 + 2][nn] = __expf(rb[i].z + smin * nm.z - RM) * RI;
                Bs[d][mq * 4 + 3][nn] = __expf(rb[i].w + smin * nm.w - RM) * RI;
            }
        }
        __syncthreads();
    }

    #pragma unroll
    for (int i = 0; i < 8; i++) {
        float2 v0 = up2(acc[i][0]), v1 = up2(acc[i][1]);
        float2 v2 = up2(acc[i][2]), v3 = up2(acc[i][3]);
        float4 o0 = {v0.x, v0.y, v1.x, v1.y};
        float4 o1 = {v2.x, v2.y, v3.x, v3.y};
        float* row = O + ((ty * 8 + i) * HH + h) * N + n0;
        *(float4*)(row + tx * 4) = o0;
        *(float4*)(row + 64 + tx * 4) = o1;
    }
}

// Merge projection: out = Wm @ (x1 + x2) + bm
__global__ __launch_bounds__(128) void merge_kernel(
    const float* __restrict__ W, const float* __restrict__ bm,
    const float* __restrict__ X1, const float* __restrict__ X2,
    float* __restrict__ O)
{
    __shared__ float As[2][16][64];
    __shared__ float Bs[2][16][132];
    const int tid = threadIdx.x, tx = tid & 15, ty = tid >> 4;
    const int n0 = blockIdx.x * 128, m0 = blockIdx.y * 64;

    ull acc[8][4];
    #pragma unroll
    for (int i = 0; i < 8; i++)
        #pragma unroll
        for (int j = 0; j < 4; j++) acc[i][j] = 0ull;

    const int ao = tid >> 1, ac = (tid & 1) * 8;
    const float* Ap = W + (m0 + ao) * DM + ac;
    const int brow = tid >> 5, bc4 = tid & 31;
    const float* B1 = X1 + brow * N + n0 + bc4 * 4;
    const float* B2 = X2 + brow * N + n0 + bc4 * 4;

    float4 ra0, ra1, rb[4];
    ra0 = *(const float4*)(Ap);
    ra1 = *(const float4*)(Ap + 4);
    #pragma unroll
    for (int i = 0; i < 4; i++) {
        float4 a = *(const float4*)(B1 + (i * 4) * N);
        float4 b = *(const float4*)(B2 + (i * 4) * N);
        rb[i] = make_float4(a.x + b.x, a.y + b.y, a.z + b.z, a.w + b.w);
    }
    {
        As[0][ac + 0][ao] = ra0.x; As[0][ac + 1][ao] = ra0.y;
        As[0][ac + 2][ao] = ra0.z; As[0][ac + 3][ao] = ra0.w;
        As[0][ac + 4][ao] = ra1.x; As[0][ac + 5][ao] = ra1.y;
        As[0][ac + 6][ao] = ra1.z; As[0][ac + 7][ao] = ra1.w;
        #pragma unroll
        for (int i = 0; i < 4; i++)
            *(float4*)&Bs[0][brow + i * 4][bc4 * 4] = rb[i];
    }
    __syncthreads();

    const int KT = DM / 16;
    for (int kt = 0; kt < KT; kt++) {
        const int s = kt & 1;
        if (kt + 1 < KT) {
            const int c0 = (kt + 1) * 16;
            ra0 = *(const float4*)(Ap + c0);
            ra1 = *(const float4*)(Ap + c0 + 4);
            #pragma unroll
            for (int i = 0; i < 4; i++) {
                float4 a = *(const float4*)(B1 + (c0 + i * 4) * N);
                float4 b = *(const float4*)(B2 + (c0 + i * 4) * N);
                rb[i] = make_float4(a.x + b.x, a.y + b.y, a.z + b.z, a.w + b.w);
            }
        }
        gemm16(As[s], Bs[s], acc, tx, ty);
        if (kt + 1 < KT) {
            const int d = s ^ 1;
            As[d][ac + 0][ao] = ra0.x; As[d][ac + 1][ao] = ra0.y;
            As[d][ac + 2][ao] = ra0.z; As[d][ac + 3][ao] = ra0.w;
            As[d][ac + 4][ao] = ra1.x; As[d][ac + 5][ao] = ra1.y;
            As[d][ac + 6][ao] = ra1.z; As[d][ac + 7][ao] = ra1.w;
            #pragma unroll
            for (int i = 0; i < 4; i++)
                *(float4*)&Bs[d][brow + i * 4][bc4 * 4] = rb[i];
        }
        __syncthreads();
    }

    #pragma unroll
    for (int i = 0; i < 8; i++) {
        float bias = bm[m0 + ty * 8 + i];
        float2 v0 = up2(acc[i][0]), v1 = up2(acc[i][1]);
        float2 v2 = up2(acc[i][2]), v3 = up2(acc[i][3]);
        float4 o0 = {v0.x + bias, v0.y + bias, v1.x + bias, v1.y + bias};
        float4 o1 = {v2.x + bias, v2.y + bias, v3.x + bias, v3.y + bias};
        float* row = O + (m0 + ty * 8 + i) * N + n0;
        *(float4*)(row + tx * 4) = o0;
        *(float4*)(row + 64 + tx * 4) = o1;
    }
}

// ---------------- launch ----------------
extern "C" void kernel_launch(void* const* d_in, const int* in_sizes, int n_in,
                              void* d_out, int out_size) {
    const float* query = (const float*)d_in[0];
    const float* key   = (const float*)d_in[1];
    const float* value = (const float*)d_in[2];
    const void*  mask  = d_in[4];
    const float* Wq = (const float*)d_in[5];
    const float* bq = (const float*)d_in[6];
    const float* Wk = (const float*)d_in[7];
    const float* bk = (const float*)d_in[8];
    const float* Wv = (const float*)d_in[9];
    const float* bv = (const float*)d_in[10];
    const float* Wm = (const float*)d_in[11];
    const float* bm = (const float*)d_in[12];
    float* out = (float*)d_out;

    float *qp, *kp, *vp, *x1p, *x2p, *Sp;
    cudaGetSymbolAddress((void**)&qp, g_q);
    cudaGetSymbolAddress((void**)&kp, g_k);
    cudaGetSymbolAddress((void**)&vp, g_v);
    cudaGetSymbolAddress((void**)&x1p, g_x1);
    cudaGetSymbolAddress((void**)&x2p, g_x2);
    cudaGetSymbolAddress((void**)&Sp, g_S);

    init_kernel<<<1, 1>>>();
    mask_detect_kernel<<<128, 256>>>((const unsigned*)mask);

    qkv_kernel<<<dim3(N / 128, DM / 64, 3), 128>>>(
        Wq, Wk, Wv, bq, bk, bv, query, key, value, qp, kp, vp);

    scores_kernel<<<dim3(N / 128, N / 64, HH), 128>>>(qp, kp, Sp);

    stats_kernel<<<N, 256>>>(Sp, mask, out + DM * N);

    pv_kernel<<<dim3(N / 128, 2, HH), 128>>>(Sp, vp, mask, x1p, x2p);

    merge_kernel<<<dim3(N / 128, DM / 64), 128>>>(Wm, bm, x1p, x2p, out);
}

// round 3
// speedup vs baseline: 1.6810x; 1.0001x over previous
#include <cuda_runtime.h>

#define N      2048
#define DM     512
#define HH     8
#define NN     (N * N)

typedef unsigned long long ull;

// ---------------- device scratch (static, allocation-free) ----------------
__device__ float    g_q[DM * N];
__device__ float    g_k[DM * N];
__device__ float    g_v[DM * N];
__device__ float    g_x1[DM * N];   // PV partial (m in [0,1024))
__device__ float    g_x2[DM * N];   // PV partial (m in [1024,2048))
__device__ float    g_S[HH * NN];   // raw scores, scaled by 1/8
__device__ float    g_rmax[HH * N]; // per-(h,n) row max of masked scores
__device__ float    g_rinv[HH * N]; // per-(h,n) 1/sum(exp)
__device__ unsigned g_smin_enc;
__device__ unsigned g_mask_or;

// ---------------- helpers ----------------
__device__ __forceinline__ unsigned enc_f(float x) {
    unsigned u = __float_as_uint(x);
    return (u & 0x80000000u) ? ~u : (u | 0x80000000u);
}
__device__ __forceinline__ float dec_f(unsigned u) {
    return (u & 0x80000000u) ? __uint_as_float(u & 0x7FFFFFFFu)
                             : __uint_as_float(~u);
}
__device__ __forceinline__ float mask_not(const void* mask, int i) {
    unsigned o = g_mask_or;
    bool mv;
    if (o == 0x3F800000u)      mv = ((const float*)mask)[i] != 0.0f;
    else if (o == 1u)          mv = ((const int*)mask)[i] != 0;
    else                       mv = ((const unsigned char*)mask)[i] != 0;
    return mv ? 0.0f : 1.0f;
}
__device__ __forceinline__ float4 mask_not4(const void* mask, int i) {
    unsigned o = g_mask_or;
    float4 r;
    if (o == 0x3F800000u) {
        float4 m = *(const float4*)((const float*)mask + i);
        r.x = m.x != 0.0f ? 0.f : 1.f; r.y = m.y != 0.0f ? 0.f : 1.f;
        r.z = m.z != 0.0f ? 0.f : 1.f; r.w = m.w != 0.0f ? 0.f : 1.f;
    } else if (o == 1u) {
        int4 m = *(const int4*)((const int*)mask + i);
        r.x = m.x ? 0.f : 1.f; r.y = m.y ? 0.f : 1.f;
        r.z = m.z ? 0.f : 1.f; r.w = m.w ? 0.f : 1.f;
    } else {
        uchar4 m = *(const uchar4*)((const unsigned char*)mask + i);
        r.x = m.x ? 0.f : 1.f; r.y = m.y ? 0.f : 1.f;
        r.z = m.z ? 0.f : 1.f; r.w = m.w ? 0.f : 1.f;
    }
    return r;
}

// packed fp32x2 FMA (Blackwell dual-rate fp32 path; ptxas never emits it from C++)
__device__ __forceinline__ void ffma2(ull& d, ull a, ull b) {
    asm("fma.rn.f32x2 %0, %1, %2, %0;" : "+l"(d) : "l"(a), "l"(b));
}
__device__ __forceinline__ ull pk2(float x, float y) {
    ull r; asm("mov.b64 %0, {%1, %2};" : "=l"(r) : "f"(x), "f"(y)); return r;
}
__device__ __forceinline__ float2 up2(ull p) {
    float2 r; asm("mov.b64 {%0, %1}, %2;" : "=f"(r.x), "=f"(r.y) : "l"(p)); return r;
}

// 16-deep K-slab of a 64(M)x128(N) tile: 128 threads, 8x8 per thread.
// N-fragment is split into two 64-wide halves (cols tx*4 and 64+tx*4)
// so LDS.128 reads are bank-conflict-free.
__device__ __forceinline__ void gemm16(const float (*__restrict__ As)[64],
                                       const float (*__restrict__ Bs)[132],
                                       ull acc[8][4], int tx, int ty) {
    #pragma unroll
    for (int k = 0; k < 16; k++) {
        float4 a0 = *(const float4*)&As[k][ty * 8];
        float4 a1 = *(const float4*)&As[k][ty * 8 + 4];
        float4 b0 = *(const float4*)&Bs[k][tx * 4];
        float4 b1 = *(const float4*)&Bs[k][64 + tx * 4];
        ull pb0 = pk2(b0.x, b0.y), pb1 = pk2(b0.z, b0.w);
        ull pb2 = pk2(b1.x, b1.y), pb3 = pk2(b1.z, b1.w);
        float av[8] = {a0.x, a0.y, a0.z, a0.w, a1.x, a1.y, a1.z, a1.w};
        #pragma unroll
        for (int i = 0; i < 8; i++) {
            ull pa = pk2(av[i], av[i]);
            ffma2(acc[i][0], pa, pb0);
            ffma2(acc[i][1], pa, pb1);
            ffma2(acc[i][2], pa, pb2);
            ffma2(acc[i][3], pa, pb3);
        }
    }
}

// ---------------- kernels ----------------

__global__ void init_kernel() {
    g_smin_enc = 0xFFFFFFFFu;
    g_mask_or  = 0u;
}

__global__ void mask_detect_kernel(const unsigned* __restrict__ m) {
    __shared__ unsigned sh[256];
    unsigned acc = 0;
    const int total = NN / 4;
    for (int i = blockIdx.x * blockDim.x + threadIdx.x; i < total;
         i += gridDim.x * blockDim.x)
        acc |= m[i];
    sh[threadIdx.x] = acc;
    __syncthreads();
    for (int s = 128; s > 0; s >>= 1) {
        if (threadIdx.x < s) sh[threadIdx.x] |= sh[threadIdx.x + s];
        __syncthreads();
    }
    if (threadIdx.x == 0) atomicOr(&g_mask_or, sh[0]);
}

// Fused q/k/v projections: z picks which. C[64 x 128 tile] = W @ X + b.
__global__ __launch_bounds__(128) void qkv_kernel(
    const float* __restrict__ Wq, const float* __restrict__ Wk,
    const float* __restrict__ Wv, const float* __restrict__ bq,
    const float* __restrict__ bk, const float* __restrict__ bv,
    const float* __restrict__ Xq, const float* __restrict__ Xk,
    const float* __restrict__ Xv,
    float* __restrict__ Oq, float* __restrict__ Ok, float* __restrict__ Ov)
{
    const float *W, *Bv_, *X;
    float* O;
    if (blockIdx.z == 0)      { W = Wq; Bv_ = bq; X = Xq; O = Oq; }
    else if (blockIdx.z == 1) { W = Wk; Bv_ = bk; X = Xk; O = Ok; }
    else                      { W = Wv; Bv_ = bv; X = Xv; O = Ov; }

    __shared__ float As[2][16][64];
    __shared__ float Bs[2][16][132];
    const int tid = threadIdx.x, tx = tid & 15, ty = tid >> 4;
    const int n0 = blockIdx.x * 128, m0 = blockIdx.y * 64;

    ull acc[8][4];
    #pragma unroll
    for (int i = 0; i < 8; i++)
        #pragma unroll
        for (int j = 0; j < 4; j++) acc[i][j] = 0ull;

    const int ao = tid >> 1, ac = (tid & 1) * 8;
    const float* Ap = W + (m0 + ao) * DM + ac;
    const int brow = tid >> 5, bc4 = tid & 31;
    const float* Bp = X + brow * N + n0 + bc4 * 4;

    float4 ra0, ra1, rb[4];
    ra0 = *(const float4*)(Ap);
    ra1 = *(const float4*)(Ap + 4);
    #pragma unroll
    for (int i = 0; i < 4; i++)
        rb[i] = *(const float4*)(Bp + (i * 4) * N);
    {
        As[0][ac + 0][ao] = ra0.x; As[0][ac + 1][ao] = ra0.y;
        As[0][ac + 2][ao] = ra0.z; As[0][ac + 3][ao] = ra0.w;
        As[0][ac + 4][ao] = ra1.x; As[0][ac + 5][ao] = ra1.y;
        As[0][ac + 6][ao] = ra1.z; As[0][ac + 7][ao] = ra1.w;
        #pragma unroll
        for (int i = 0; i < 4; i++)
            *(float4*)&Bs[0][brow + i * 4][bc4 * 4] = rb[i];
    }
    __syncthreads();

    const int KT = DM / 16;
    for (int kt = 0; kt < KT; kt++) {
        const int s = kt & 1;
        if (kt + 1 < KT) {
            const int c0 = (kt + 1) * 16;
            ra0 = *(const float4*)(Ap + c0);
            ra1 = *(const float4*)(Ap + c0 + 4);
            #pragma unroll
            for (int i = 0; i < 4; i++)
                rb[i] = *(const float4*)(Bp + (c0 + i * 4) * N);
        }
        gemm16(As[s], Bs[s], acc, tx, ty);
        if (kt + 1 < KT) {
            const int d = s ^ 1;
            As[d][ac + 0][ao] = ra0.x; As[d][ac + 1][ao] = ra0.y;
            As[d][ac + 2][ao] = ra0.z; As[d][ac + 3][ao] = ra0.w;
            As[d][ac + 4][ao] = ra1.x; As[d][ac + 5][ao] = ra1.y;
            As[d][ac + 6][ao] = ra1.z; As[d][ac + 7][ao] = ra1.w;
            #pragma unroll
            for (int i = 0; i < 4; i++)
                *(float4*)&Bs[d][brow + i * 4][bc4 * 4] = rb[i];
        }
        __syncthreads();
    }

    #pragma unroll
    for (int i = 0; i < 8; i++) {
        float bias = Bv_[m0 + ty * 8 + i];
        float2 v0 = up2(acc[i][0]), v1 = up2(acc[i][1]);
        float2 v2 = up2(acc[i][2]), v3 = up2(acc[i][3]);
        float4 o0 = {v0.x + bias, v0.y + bias, v1.x + bias, v1.y + bias};
        float4 o1 = {v2.x + bias, v2.y + bias, v3.x + bias, v3.y + bias};
        float* row = O + (m0 + ty * 8 + i) * N + n0;
        *(float4*)(row + tx * 4) = o0;
        *(float4*)(row + 64 + tx * 4) = o1;
    }
}

// S[h][n][m] tile [n=64][m=128], K = d = 64. Also global min (atomicMin).
__global__ __launch_bounds__(128) void scores_kernel(
    const float* __restrict__ q, const float* __restrict__ k,
    float* __restrict__ S)
{
    __shared__ float As[2][16][64];
    __shared__ float Bs[2][16][132];
    __shared__ float red[4];
    const int tid = threadIdx.x, tx = tid & 15, ty = tid >> 4;
    const int m0 = blockIdx.x * 128, n0 = blockIdx.y * 64;
    const int h = blockIdx.z;

    ull acc[8][4];
    #pragma unroll
    for (int i = 0; i < 8; i++)
        #pragma unroll
        for (int j = 0; j < 4; j++) acc[i][j] = 0ull;

    const int ad = tid >> 3, anq = tid & 7;       // A: 16 d rows x 64 n
    const float* Ap = q + (ad * HH + h) * N + n0 + anq * 8;
    const int brow = tid >> 5, bc4 = tid & 31;    // B: 16 d rows x 128 m
    const float* Bp = k + (brow * HH + h) * N + m0 + bc4 * 4;
    const int dstep = 16 * HH * N;                // advance 16 channels

    float4 ra0, ra1, rb[4];
    ra0 = *(const float4*)(Ap);
    ra1 = *(const float4*)(Ap + 4);
    #pragma unroll
    for (int i = 0; i < 4; i++)
        rb[i] = *(const float4*)(Bp + i * 4 * HH * N);
    {
        *(float4*)&As[0][ad][anq * 8] = ra0;
        *(float4*)&As[0][ad][anq * 8 + 4] = ra1;
        #pragma unroll
        for (int i = 0; i < 4; i++)
            *(float4*)&Bs[0][brow + i * 4][bc4 * 4] = rb[i];
    }
    __syncthreads();

    const int KT = 4;  // 64 / 16
    for (int kt = 0; kt < KT; kt++) {
        const int s = kt & 1;
        if (kt + 1 < KT) {
            const int off = (kt + 1) * dstep;
            ra0 = *(const float4*)(Ap + off);
            ra1 = *(const float4*)(Ap + off + 4);
            #pragma unroll
            for (int i = 0; i < 4; i++)
                rb[i] = *(const float4*)(Bp + off + i * 4 * HH * N);
        }
        gemm16(As[s], Bs[s], acc, tx, ty);
        if (kt + 1 < KT) {
            const int d = s ^ 1;
            *(float4*)&As[d][ad][anq * 8] = ra0;
            *(float4*)&As[d][ad][anq * 8 + 4] = ra1;
            #pragma unroll
            for (int i = 0; i < 4; i++)
                *(float4*)&Bs[d][brow + i * 4][bc4 * 4] = rb[i];
        }
        __syncthreads();
    }

    float lmin = 3.0e38f;
    float* base = S + h * NN;
    #pragma unroll
    for (int i = 0; i < 8; i++) {
        float2 v0 = up2(acc[i][0]), v1 = up2(acc[i][1]);
        float2 v2 = up2(acc[i][2]), v3 = up2(acc[i][3]);
        float4 o0 = {v0.x * 0.125f, v0.y * 0.125f, v1.x * 0.125f, v1.y * 0.125f};
        float4 o1 = {v2.x * 0.125f, v2.y * 0.125f, v3.x * 0.125f, v3.y * 0.125f};
        float* row = base + (n0 + ty * 8 + i) * N + m0;
        *(float4*)(row + tx * 4) = o0;
        *(float4*)(row + 64 + tx * 4) = o1;
        lmin = fminf(lmin, fminf(fminf(o0.x, o0.y), fminf(o0.z, o0.w)));
        lmin = fminf(lmin, fminf(fminf(o1.x, o1.y), fminf(o1.z, o1.w)));
    }
    #pragma unroll
    for (int o = 16; o > 0; o >>= 1)
        lmin = fminf(lmin, __shfl_xor_sync(~0u, lmin, o));
    if ((tid & 31) == 0) red[tid >> 5] = lmin;
    __syncthreads();
    if (tid == 0) {
        float m = fminf(fminf(red[0], red[1]), fminf(red[2], red[3]));
        atomicMin(&g_smin_enc, enc_f(m));
    }
}

// Per-n row: softmax stats for all 8 heads + head-mean output (out2).
__global__ __launch_bounds__(256) void stats_kernel(
    const float* __restrict__ S, const void* __restrict__ mask,
    float* __restrict__ out2)
{
    __shared__ float notm[N];
    __shared__ float red[8];
    const int n = blockIdx.x, tid = threadIdx.x;
    for (int j = tid; j < N; j += 256) notm[j] = mask_not(mask, n * N + j);
    __syncthreads();
    const float smin = dec_f(g_smin_enc);
    float msum[8] = {0, 0, 0, 0, 0, 0, 0, 0};
    #pragma unroll 1
    for (int h = 0; h < HH; h++) {
        const float* row = S + h * NN + n * N;
        float v[8], mx = -3.0e38f;
        #pragma unroll
        for (int i = 0; i < 8; i++) {
            int j = tid + i * 256;
            float s = row[j];
            msum[i] += s;
            float t = s + smin * notm[j];
            v[i] = t;
            mx = fmaxf(mx, t);
        }
        #pragma unroll
        for (int o = 16; o > 0; o >>= 1)
            mx = fmaxf(mx, __shfl_xor_sync(~0u, mx, o));
        if ((tid & 31) == 0) red[tid >> 5] = mx;
        __syncthreads();
        float MX = red[0];
        #pragma unroll
        for (int w = 1; w < 8; w++) MX = fmaxf(MX, red[w]);
        __syncthreads();
        float sum = 0.0f;
        #pragma unroll
        for (int i = 0; i < 8; i++) sum += __expf(v[i] - MX);
        #pragma unroll
        for (int o = 16; o > 0; o >>= 1)
            sum += __shfl_xor_sync(~0u, sum, o);
        if ((tid & 31) == 0) red[tid >> 5] = sum;
        __syncthreads();
        float SUM = 0.0f;
        #pragma unroll
        for (int w = 0; w < 8; w++) SUM += red[w];
        if (tid == 0) {
            g_rmax[h * N + n] = MX;
            g_rinv[h * N + n] = 1.0f / SUM;
        }
        __syncthreads();
    }
    #pragma unroll
    for (int i = 0; i < 8; i++) {
        int j = tid + i * 256;
        out2[n * N + j] = msum[i] * 0.125f + smin * notm[j];
    }
}

// PV with on-the-fly softmax: x[(d*8+h)][n] = sum_m P[h][n][m] v[(d*8+h)][m]
// Tile [d=64][n=128], K = m split in halves (blockIdx.y) into g_x1/g_x2.
__global__ __launch_bounds__(128) void pv_kernel(
    const float* __restrict__ S, const float* __restrict__ v,
    const void* __restrict__ mask,
    float* __restrict__ X1, float* __restrict__ X2)
{
    __shared__ float As[2][16][64];
    __shared__ float Bs[2][16][132];
    __shared__ float rm[128], ri[128];
    const int tid = threadIdx.x, tx = tid & 15, ty = tid >> 4;
    const int n0 = blockIdx.x * 128;
    const int mbase = blockIdx.y * (N / 2);
    const int h = blockIdx.z;
    float* O = blockIdx.y ? X2 : X1;

    rm[tid] = g_rmax[h * N + n0 + tid];
    ri[tid] = g_rinv[h * N + n0 + tid];
    const float smin = dec_f(g_smin_enc);

    ull acc[8][4];
    #pragma unroll
    for (int i = 0; i < 8; i++)
        #pragma unroll
        for (int j = 0; j < 4; j++) acc[i][j] = 0ull;

    const int ad = tid >> 1, am8 = (tid & 1) * 8;   // A: 64 d x 16 m (transpose)
    const float* Vp = v + (ad * HH + h) * N + mbase + am8;
    const int bn = tid >> 2, bmq = tid & 3;          // B: per thread 4 iters
    const float* Sb = S + h * NN + n0 * N + mbase;

    float4 ra0, ra1, rb[4];
    int rbn[4];
    // prefetch tile 0 (c0 = 0)
    ra0 = *(const float4*)(Vp);
    ra1 = *(const float4*)(Vp + 4);
    #pragma unroll
    for (int i = 0; i < 4; i++) {
        int idx = tid + i * 128;
        int nn = idx >> 2, mq = idx & 3;
        rbn[i] = nn;
        rb[i] = *(const float4*)(Sb + nn * N + mq * 4);
    }
    __syncthreads();  // rm/ri visible
    {
        As[0][am8 + 0][ad] = ra0.x; As[0][am8 + 1][ad] = ra0.y;
        As[0][am8 + 2][ad] = ra0.z; As[0][am8 + 3][ad] = ra0.w;
        As[0][am8 + 4][ad] = ra1.x; As[0][am8 + 5][ad] = ra1.y;
        As[0][am8 + 6][ad] = ra1.z; As[0][am8 + 7][ad] = ra1.w;
        #pragma unroll
        for (int i = 0; i < 4; i++) {
            int idx = tid + i * 128;
            int nn = idx >> 2, mq = idx & 3;
            float4 nm = mask_not4(mask, (n0 + nn) * N + mbase + mq * 4);
            float RM = rm[nn], RI = ri[nn];
            Bs[0][mq * 4 + 0][nn] = __expf(rb[i].x + smin * nm.x - RM) * RI;
            Bs[0][mq * 4 + 1][nn] = __expf(rb[i].y + smin * nm.y - RM) * RI;
            Bs[0][mq * 4 + 2][nn] = __expf(rb[i].z + smin * nm.z - RM) * RI;
            Bs[0][mq * 4 + 3][nn] = __expf(rb[i].w + smin * nm.w - RM) * RI;
        }
    }
    __syncthreads();

    const int KT = (N / 2) / 16;  // 64
    for (int kt = 0; kt < KT; kt++) {
        const int s = kt & 1;
        const int c1 = (kt + 1) * 16;
        if (kt + 1 < KT) {
            ra0 = *(const float4*)(Vp + c1);
            ra1 = *(const float4*)(Vp + c1 + 4);
            #pragma unroll
            for (int i = 0; i < 4; i++) {
                int idx = tid + i * 128;
                int nn = idx >> 2, mq = idx & 3;
                rb[i] = *(const float4*)(Sb + nn * N + c1 + mq * 4);
            }
        }
        gemm16(As[s], Bs[s], acc, tx, ty);
        if (kt + 1 < KT) {
            const int d = s ^ 1;
            As[d][am8 + 0][ad] = ra0.x; As[d][am8 + 1][ad] = ra0.y;
            As[d][am8 + 2][ad] = ra0.z; As[d][am8 + 3][ad] = ra0.w;
            As[d][am8 + 4][ad] = ra1.x; As[d][am8 + 5][ad] = ra1.y;
            As[d][am8 + 6][ad] = ra1.z; As[d][am8 + 7][ad] = ra1.w;
            #pragma unroll
            for (int i = 0; i < 4; i++) {
                int idx = tid + i * 128;
                int nn = idx >> 2, mq = idx & 3;
                float4 nm = mask_not4(mask, (n0 + nn) * N + mbase + c1 + mq * 4);
                float RM = rm[nn], RI = ri[nn];
                Bs[d][mq * 4 + 0][nn] = __expf(rb[i].x + smin * nm.x - RM) * RI;
                Bs[d][mq * 4 + 1][nn] = __expf(rb[i].y + smin * nm.y - RM) * RI;
                Bs[d][mq * 4 + 2][nn] = __expf(rb[i].z + smin * nm.z - RM) * RI;
                Bs[d][mq * 4 + 3][nn] = __expf(rb[i].w + smin * nm.w - RM) * RI;
            }
        }
        __syncthreads();
    }

    #pragma unroll
    for (int i = 0; i < 8; i++) {
        float2 v0 = up2(acc[i][0]), v1 = up2(acc[i][1]);
        float2 v2 = up2(acc[i][2]), v3 = up2(acc[i][3]);
        float4 o0 = {v0.x, v0.y, v1.x, v1.y};
        float4 o1 = {v2.x, v2.y, v3.x, v3.y};
        float* row = O + ((ty * 8 + i) * HH + h) * N + n0;
        *(float4*)(row + tx * 4) = o0;
        *(float4*)(row + 64 + tx * 4) = o1;
    }
}

// Merge projection: out = Wm @ (x1 + x2) + bm
__global__ __launch_bounds__(128) void merge_kernel(
    const float* __restrict__ W, const float* __restrict__ bm,
    const float* __restrict__ X1, const float* __restrict__ X2,
    float* __restrict__ O)
{
    __shared__ float As[2][16][64];
    __shared__ float Bs[2][16][132];
    const int tid = threadIdx.x, tx = tid & 15, ty = tid >> 4;
    const int n0 = blockIdx.x * 128, m0 = blockIdx.y * 64;

    ull acc[8][4];
    #pragma unroll
    for (int i = 0; i < 8; i++)
        #pragma unroll
        for (int j = 0; j < 4; j++) acc[i][j] = 0ull;

    const int ao = tid >> 1, ac = (tid & 1) * 8;
    const float* Ap = W + (m0 + ao) * DM + ac;
    const int brow = tid >> 5, bc4 = tid & 31;
    const float* B1 = X1 + brow * N + n0 + bc4 * 4;
    const float* B2 = X2 + brow * N + n0 + bc4 * 4;

    float4 ra0, ra1, rb[4];
    ra0 = *(const float4*)(Ap);
    ra1 = *(const float4*)(Ap + 4);
    #pragma unroll
    for (int i = 0; i < 4; i++) {
        float4 a = *(const float4*)(B1 + (i * 4) * N);
        float4 b = *(const float4*)(B2 + (i * 4) * N);
        rb[i] = make_float4(a.x + b.x, a.y + b.y, a.z + b.z, a.w + b.w);
    }
    {
        As[0][ac + 0][ao] = ra0.x; As[0][ac + 1][ao] = ra0.y;
        As[0][ac + 2][ao] = ra0.z; As[0][ac + 3][ao] = ra0.w;
        As[0][ac + 4][ao] = ra1.x; As[0][ac + 5][ao] = ra1.y;
        As[0][ac + 6][ao] = ra1.z; As[0][ac + 7][ao] = ra1.w;
        #pragma unroll
        for (int i = 0; i < 4; i++)
            *(float4*)&Bs[0][brow + i * 4][bc4 * 4] = rb[i];
    }
    __syncthreads();

    const int KT = DM / 16;
    for (int kt = 0; kt < KT; kt++) {
        const int s = kt & 1;
        if (kt + 1 < KT) {
            const int c0 = (kt + 1) * 16;
            ra0 = *(const float4*)(Ap + c0);
            ra1 = *(const float4*)(Ap + c0 + 4);
            #pragma unroll
            for (int i = 0; i < 4; i++) {
                float4 a = *(const float4*)(B1 + (c0 + i * 4) * N);
                float4 b = *(const float4*)(B2 + (c0 + i * 4) * N);
                rb[i] = make_float4(a.x + b.x, a.y + b.y, a.z + b.z, a.w + b.w);
            }
        }
        gemm16(As[s], Bs[s], acc, tx, ty);
        if (kt + 1 < KT) {
            const int d = s ^ 1;
            As[d][ac + 0][ao] = ra0.x; As[d][ac + 1][ao] = ra0.y;
            As[d][ac + 2][ao] = ra0.z; As[d][ac + 3][ao] = ra0.w;
            As[d][ac + 4][ao] = ra1.x; As[d][ac + 5][ao] = ra1.y;
            As[d][ac + 6][ao] = ra1.z; As[d][ac + 7][ao] = ra1.w;
            #pragma unroll
            for (int i = 0; i < 4; i++)
                *(float4*)&Bs[d][brow + i * 4][bc4 * 4] = rb[i];
        }
        __syncthreads();
    }

    #pragma unroll
    for (int i = 0; i < 8; i++) {
        float bias = bm[m0 + ty * 8 + i];
        float2 v0 = up2(acc[i][0]), v1 = up2(acc[i][1]);
        float2 v2 = up2(acc[i][2]), v3 = up2(acc[i][3]);
        float4 o0 = {v0.x + bias, v0.y + bias, v1.x + bias, v1.y + bias};
        float4 o1 = {v2.x + bias, v2.y + bias, v3.x + bias, v3.y + bias};
        float* row = O + (m0 + ty * 8 + i) * N + n0;
        *(float4*)(row + tx * 4) = o0;
        *(float4*)(row + 64 + tx * 4) = o1;
    }
}

// ---------------- launch ----------------
extern "C" void kernel_launch(void* const* d_in, const int* in_sizes, int n_in,
                              void* d_out, int out_size) {
    const float* query = (const float*)d_in[0];
    const float* key   = (const float*)d_in[1];
    const float* value = (const float*)d_in[2];
    const void*  mask  = d_in[4];
    const float* Wq = (const float*)d_in[5];
    const float* bq = (const float*)d_in[6];
    const float* Wk = (const float*)d_in[7];
    const float* bk = (const float*)d_in[8];
    const float* Wv = (const float*)d_in[9];
    const float* bv = (const float*)d_in[10];
    const float* Wm = (const float*)d_in[11];
    const float* bm = (const float*)d_in[12];
    float* out = (float*)d_out;

    float *qp, *kp, *vp, *x1p, *x2p, *Sp;
    cudaGetSymbolAddress((void**)&qp, g_q);
    cudaGetSymbolAddress((void**)&kp, g_k);
    cudaGetSymbolAddress((void**)&vp, g_v);
    cudaGetSymbolAddress((void**)&x1p, g_x1);
    cudaGetSymbolAddress((void**)&x2p, g_x2);
    cudaGetSymbolAddress((void**)&Sp, g_S);

    init_kernel<<<1, 1>>>();
    mask_detect_kernel<<<128, 256>>>((const unsigned*)mask);

    qkv_kernel<<<dim3(N / 128, DM / 64, 3), 128>>>(
        Wq, Wk, Wv, bq, bk, bv, query, key, value, qp, kp, vp);

    scores_kernel<<<dim3(N / 128, N / 64, HH), 128>>>(qp, kp, Sp);

    stats_kernel<<<N, 256>>>(Sp, mask, out + DM * N);

    pv_kernel<<<dim3(N / 128, 2, HH), 128>>>(Sp, vp, mask, x1p, x2p);

    merge_kernel<<<dim3(N / 128, DM / 64), 128>>>(Wm, bm, x1p, x2p, out);
}

// round 4
// speedup vs baseline: 1.6853x; 1.0025x over previous
#include <cuda_runtime.h>

#define N      2048
#define DM     512
#define HH     8
#define NN     (N * N)

typedef unsigned long long ull;

// ---------------- device scratch (static, allocation-free) ----------------
__device__ float    g_q[DM * N];
__device__ float    g_k[DM * N];
__device__ float    g_v[DM * N];
__device__ float    g_x1[DM * N];   // PV partial (m in [0,1024))
__device__ float    g_x2[DM * N];   // PV partial (m in [1024,2048))
__device__ float    g_S[HH * NN];   // raw scores, scaled by 1/8
__device__ float    g_rmax[HH * N]; // per-(h,n) row max of masked scores
__device__ float    g_rinv[HH * N]; // per-(h,n) 1/sum(exp)
__device__ unsigned g_smin_enc;
__device__ unsigned g_mask_or;

// ---------------- helpers ----------------
__device__ __forceinline__ unsigned enc_f(float x) {
    unsigned u = __float_as_uint(x);
    return (u & 0x80000000u) ? ~u : (u | 0x80000000u);
}
__device__ __forceinline__ float dec_f(unsigned u) {
    return (u & 0x80000000u) ? __uint_as_float(u & 0x7FFFFFFFu)
                             : __uint_as_float(~u);
}
__device__ __forceinline__ float mask_not(const void* mask, int i) {
    unsigned o = g_mask_or;
    bool mv;
    if (o == 0x3F800000u)      mv = ((const float*)mask)[i] != 0.0f;
    else if (o == 1u)          mv = ((const int*)mask)[i] != 0;
    else                       mv = ((const unsigned char*)mask)[i] != 0;
    return mv ? 0.0f : 1.0f;
}
__device__ __forceinline__ float4 mask_not4(const void* mask, int i) {
    unsigned o = g_mask_or;
    float4 r;
    if (o == 0x3F800000u) {
        float4 m = *(const float4*)((const float*)mask + i);
        r.x = m.x != 0.0f ? 0.f : 1.f; r.y = m.y != 0.0f ? 0.f : 1.f;
        r.z = m.z != 0.0f ? 0.f : 1.f; r.w = m.w != 0.0f ? 0.f : 1.f;
    } else if (o == 1u) {
        int4 m = *(const int4*)((const int*)mask + i);
        r.x = m.x ? 0.f : 1.f; r.y = m.y ? 0.f : 1.f;
        r.z = m.z ? 0.f : 1.f; r.w = m.w ? 0.f : 1.f;
    } else {
        uchar4 m = *(const uchar4*)((const unsigned char*)mask + i);
        r.x = m.x ? 0.f : 1.f; r.y = m.y ? 0.f : 1.f;
        r.z = m.z ? 0.f : 1.f; r.w = m.w ? 0.f : 1.f;
    }
    return r;
}

// packed fp32x2 FMA (Blackwell dual-rate fp32 path; ptxas never emits it from C++)
__device__ __forceinline__ void ffma2(ull& d, ull a, ull b) {
    asm("fma.rn.f32x2 %0, %1, %2, %0;" : "+l"(d) : "l"(a), "l"(b));
}
__device__ __forceinline__ ull pk2(float x, float y) {
    ull r; asm("mov.b64 %0, {%1, %2};" : "=l"(r) : "f"(x), "f"(y)); return r;
}
__device__ __forceinline__ float2 up2(ull p) {
    float2 r; asm("mov.b64 {%0, %1}, %2;" : "=f"(r.x), "=f"(r.y) : "l"(p)); return r;
}

// 16-deep K-slab of a 64(M)x128(N) tile: 128 threads, 8x8 per thread.
// N-fragment is split into two 64-wide halves (cols tx*4 and 64+tx*4)
// so LDS.128 reads are bank-conflict-free.
__device__ __forceinline__ void gemm16(const float (*__restrict__ As)[64],
                                       const float (*__restrict__ Bs)[132],
                                       ull acc[8][4], int tx, int ty) {
    #pragma unroll
    for (int k = 0; k < 16; k++) {
        float4 a0 = *(const float4*)&As[k][ty * 8];
        float4 a1 = *(const float4*)&As[k][ty * 8 + 4];
        float4 b0 = *(const float4*)&Bs[k][tx * 4];
        float4 b1 = *(const float4*)&Bs[k][64 + tx * 4];
        ull pb0 = pk2(b0.x, b0.y), pb1 = pk2(b0.z, b0.w);
        ull pb2 = pk2(b1.x, b1.y), pb3 = pk2(b1.z, b1.w);
        float av[8] = {a0.x, a0.y, a0.z, a0.w, a1.x, a1.y, a1.z, a1.w};
        #pragma unroll
        for (int i = 0; i < 8; i++) {
            ull pa = pk2(av[i], av[i]);
            ffma2(acc[i][0], pa, pb0);
            ffma2(acc[i][1], pa, pb1);
            ffma2(acc[i][2], pa, pb2);
            ffma2(acc[i][3], pa, pb3);
        }
    }
}

// ---------------- kernels ----------------

__global__ void init_kernel() {
    g_smin_enc = 0xFFFFFFFFu;
    g_mask_or  = 0u;
}

__global__ void mask_detect_kernel(const unsigned* __restrict__ m) {
    __shared__ unsigned sh[256];
    unsigned acc = 0;
    const int total = NN / 4;
    for (int i = blockIdx.x * blockDim.x + threadIdx.x; i < total;
         i += gridDim.x * blockDim.x)
        acc |= m[i];
    sh[threadIdx.x] = acc;
    __syncthreads();
    for (int s = 128; s > 0; s >>= 1) {
        if (threadIdx.x < s) sh[threadIdx.x] |= sh[threadIdx.x + s];
        __syncthreads();
    }
    if (threadIdx.x == 0) atomicOr(&g_mask_or, sh[0]);
}

// Fused q/k/v projections: z picks which. C[64 x 128 tile] = W @ X + b.
__global__ __launch_bounds__(128) void qkv_kernel(
    const float* __restrict__ Wq, const float* __restrict__ Wk,
    const float* __restrict__ Wv, const float* __restrict__ bq,
    const float* __restrict__ bk, const float* __restrict__ bv,
    const float* __restrict__ Xq, const float* __restrict__ Xk,
    const float* __restrict__ Xv,
    float* __restrict__ Oq, float* __restrict__ Ok, float* __restrict__ Ov)
{
    const float *W, *Bv_, *X;
    float* O;
    if (blockIdx.z == 0)      { W = Wq; Bv_ = bq; X = Xq; O = Oq; }
    else if (blockIdx.z == 1) { W = Wk; Bv_ = bk; X = Xk; O = Ok; }
    else                      { W = Wv; Bv_ = bv; X = Xv; O = Ov; }

    __shared__ float As[2][16][64];
    __shared__ float Bs[2][16][132];
    const int tid = threadIdx.x, tx = tid & 15, ty = tid >> 4;
    const int n0 = blockIdx.x * 128, m0 = blockIdx.y * 64;

    ull acc[8][4];
    #pragma unroll
    for (int i = 0; i < 8; i++)
        #pragma unroll
        for (int j = 0; j < 4; j++) acc[i][j] = 0ull;

    const int ao = tid >> 1, ac = (tid & 1) * 8;
    const float* Ap = W + (m0 + ao) * DM + ac;
    const int brow = tid >> 5, bc4 = tid & 31;
    const float* Bp = X + brow * N + n0 + bc4 * 4;

    float4 ra0, ra1, rb[4];
    ra0 = *(const float4*)(Ap);
    ra1 = *(const float4*)(Ap + 4);
    #pragma unroll
    for (int i = 0; i < 4; i++)
        rb[i] = *(const float4*)(Bp + (i * 4) * N);
    {
        As[0][ac + 0][ao] = ra0.x; As[0][ac + 1][ao] = ra0.y;
        As[0][ac + 2][ao] = ra0.z; As[0][ac + 3][ao] = ra0.w;
        As[0][ac + 4][ao] = ra1.x; As[0][ac + 5][ao] = ra1.y;
        As[0][ac + 6][ao] = ra1.z; As[0][ac + 7][ao] = ra1.w;
        #pragma unroll
        for (int i = 0; i < 4; i++)
            *(float4*)&Bs[0][brow + i * 4][bc4 * 4] = rb[i];
    }
    __syncthreads();

    const int KT = DM / 16;
    for (int kt = 0; kt < KT; kt++) {
        const int s = kt & 1;
        if (kt + 1 < KT) {
            const int c0 = (kt + 1) * 16;
            ra0 = *(const float4*)(Ap + c0);
            ra1 = *(const float4*)(Ap + c0 + 4);
            #pragma unroll
            for (int i = 0; i < 4; i++)
                rb[i] = *(const float4*)(Bp + (c0 + i * 4) * N);
        }
        gemm16(As[s], Bs[s], acc, tx, ty);
        if (kt + 1 < KT) {
            const int d = s ^ 1;
            As[d][ac + 0][ao] = ra0.x; As[d][ac + 1][ao] = ra0.y;
            As[d][ac + 2][ao] = ra0.z; As[d][ac + 3][ao] = ra0.w;
            As[d][ac + 4][ao] = ra1.x; As[d][ac + 5][ao] = ra1.y;
            As[d][ac + 6][ao] = ra1.z; As[d][ac + 7][ao] = ra1.w;
            #pragma unroll
            for (int i = 0; i < 4; i++)
                *(float4*)&Bs[d][brow + i * 4][bc4 * 4] = rb[i];
        }
        __syncthreads();
    }

    #pragma unroll
    for (int i = 0; i < 8; i++) {
        float bias = Bv_[m0 + ty * 8 + i];
        float2 v0 = up2(acc[i][0]), v1 = up2(acc[i][1]);
        float2 v2 = up2(acc[i][2]), v3 = up2(acc[i][3]);
        float4 o0 = {v0.x + bias, v0.y + bias, v1.x + bias, v1.y + bias};
        float4 o1 = {v2.x + bias, v2.y + bias, v3.x + bias, v3.y + bias};
        float* row = O + (m0 + ty * 8 + i) * N + n0;
        *(float4*)(row + tx * 4) = o0;
        *(float4*)(row + 64 + tx * 4) = o1;
    }
}

// S[h][n][m] tile [n=64][m=128], K = d = 64. Also global min (atomicMin).
__global__ __launch_bounds__(128) void scores_kernel(
    const float* __restrict__ q, const float* __restrict__ k,
    float* __restrict__ S)
{
    __shared__ float As[2][16][64];
    __shared__ float Bs[2][16][132];
    __shared__ float red[4];
    const int tid = threadIdx.x, tx = tid & 15, ty = tid >> 4;
    const int m0 = blockIdx.x * 128, n0 = blockIdx.y * 64;
    const int h = blockIdx.z;

    ull acc[8][4];
    #pragma unroll
    for (int i = 0; i < 8; i++)
        #pragma unroll
        for (int j = 0; j < 4; j++) acc[i][j] = 0ull;

    const int ad = tid >> 3, anq = tid & 7;       // A: 16 d rows x 64 n
    const float* Ap = q + (ad * HH + h) * N + n0 + anq * 8;
    const int brow = tid >> 5, bc4 = tid & 31;    // B: 16 d rows x 128 m
    const float* Bp = k + (brow * HH + h) * N + m0 + bc4 * 4;
    const int dstep = 16 * HH * N;                // advance 16 channels

    float4 ra0, ra1, rb[4];
    ra0 = *(const float4*)(Ap);
    ra1 = *(const float4*)(Ap + 4);
    #pragma unroll
    for (int i = 0; i < 4; i++)
        rb[i] = *(const float4*)(Bp + i * 4 * HH * N);
    {
        *(float4*)&As[0][ad][anq * 8] = ra0;
        *(float4*)&As[0][ad][anq * 8 + 4] = ra1;
        #pragma unroll
        for (int i = 0; i < 4; i++)
            *(float4*)&Bs[0][brow + i * 4][bc4 * 4] = rb[i];
    }
    __syncthreads();

    const int KT = 4;  // 64 / 16
    for (int kt = 0; kt < KT; kt++) {
        const int s = kt & 1;
        if (kt + 1 < KT) {
            const int off = (kt + 1) * dstep;
            ra0 = *(const float4*)(Ap + off);
            ra1 = *(const float4*)(Ap + off + 4);
            #pragma unroll
            for (int i = 0; i < 4; i++)
                rb[i] = *(const float4*)(Bp + off + i * 4 * HH * N);
        }
        gemm16(As[s], Bs[s], acc, tx, ty);
        if (kt + 1 < KT) {
            const int d = s ^ 1;
            *(float4*)&As[d][ad][anq * 8] = ra0;
            *(float4*)&As[d][ad][anq * 8 + 4] = ra1;
            #pragma unroll
            for (int i = 0; i < 4; i++)
                *(float4*)&Bs[d][brow + i * 4][bc4 * 4] = rb[i];
        }
        __syncthreads();
    }

    float lmin = 3.0e38f;
    float* base = S + h * NN;
    #pragma unroll
    for (int i = 0; i < 8; i++) {
        float2 v0 = up2(acc[i][0]), v1 = up2(acc[i][1]);
        float2 v2 = up2(acc[i][2]), v3 = up2(acc[i][3]);
        float4 o0 = {v0.x * 0.125f, v0.y * 0.125f, v1.x * 0.125f, v1.y * 0.125f};
        float4 o1 = {v2.x * 0.125f, v2.y * 0.125f, v3.x * 0.125f, v3.y * 0.125f};
        float* row = base + (n0 + ty * 8 + i) * N + m0;
        *(float4*)(row + tx * 4) = o0;
        *(float4*)(row + 64 + tx * 4) = o1;
        lmin = fminf(lmin, fminf(fminf(o0.x, o0.y), fminf(o0.z, o0.w)));
        lmin = fminf(lmin, fminf(fminf(o1.x, o1.y), fminf(o1.z, o1.w)));
    }
    #pragma unroll
    for (int o = 16; o > 0; o >>= 1)
        lmin = fminf(lmin, __shfl_xor_sync(~0u, lmin, o));
    if ((tid & 31) == 0) red[tid >> 5] = lmin;
    __syncthreads();
    if (tid == 0) {
        float m = fminf(fminf(red[0], red[1]), fminf(red[2], red[3]));
        atomicMin(&g_smin_enc, enc_f(m));
    }
}

// Per-n row: softmax stats for all 8 heads + head-mean output (out2).
__global__ __launch_bounds__(256) void stats_kernel(
    const float* __restrict__ S, const void* __restrict__ mask,
    float* __restrict__ out2)
{
    __shared__ float notm[N];
    __shared__ float red[8];
    const int n = blockIdx.x, tid = threadIdx.x;
    for (int j = tid; j < N; j += 256) notm[j] = mask_not(mask, n * N + j);
    __syncthreads();
    const float smin = dec_f(g_smin_enc);
    float msum[8] = {0, 0, 0, 0, 0, 0, 0, 0};
    #pragma unroll 1
    for (int h = 0; h < HH; h++) {
        const float* row = S + h * NN + n * N;
        float v[8], mx = -3.0e38f;
        #pragma unroll
        for (int i = 0; i < 8; i++) {
            int j = tid + i * 256;
            float s = row[j];
            msum[i] += s;
            float t = s + smin * notm[j];
            v[i] = t;
            mx = fmaxf(mx, t);
        }
        #pragma unroll
        for (int o = 16; o > 0; o >>= 1)
            mx = fmaxf(mx, __shfl_xor_sync(~0u, mx, o));
        if ((tid & 31) == 0) red[tid >> 5] = mx;
        __syncthreads();
        float MX = red[0];
        #pragma unroll
        for (int w = 1; w < 8; w++) MX = fmaxf(MX, red[w]);
        __syncthreads();
        float sum = 0.0f;
        #pragma unroll
        for (int i = 0; i < 8; i++) sum += __expf(v[i] - MX);
        #pragma unroll
        for (int o = 16; o > 0; o >>= 1)
            sum += __shfl_xor_sync(~0u, sum, o);
        if ((tid & 31) == 0) red[tid >> 5] = sum;
        __syncthreads();
        float SUM = 0.0f;
        #pragma unroll
        for (int w = 0; w < 8; w++) SUM += red[w];
        if (tid == 0) {
            g_rmax[h * N + n] = MX;
            g_rinv[h * N + n] = 1.0f / SUM;
        }
        __syncthreads();
    }
    #pragma unroll
    for (int i = 0; i < 8; i++) {
        int j = tid + i * 256;
        out2[n * N + j] = msum[i] * 0.125f + smin * notm[j];
    }
}

// PV with on-the-fly softmax: x[(d*8+h)][n] = sum_m P[h][n][m] v[(d*8+h)][m]
// Tile [d=64][n=128], K = m split in halves (blockIdx.y) into g_x1/g_x2.
__global__ __launch_bounds__(128) void pv_kernel(
    const float* __restrict__ S, const float* __restrict__ v,
    const void* __restrict__ mask,
    float* __restrict__ X1, float* __restrict__ X2)
{
    __shared__ float As[2][16][64];
    __shared__ float Bs[2][16][132];
    __shared__ float rm[128], ri[128];
    const int tid = threadIdx.x, tx = tid & 15, ty = tid >> 4;
    const int n0 = blockIdx.x * 128;
    const int mbase = blockIdx.y * (N / 2);
    const int h = blockIdx.z;
    float* O = blockIdx.y ? X2 : X1;

    rm[tid] = g_rmax[h * N + n0 + tid];
    ri[tid] = g_rinv[h * N + n0 + tid];
    const float smin = dec_f(g_smin_enc);

    ull acc[8][4];
    #pragma unroll
    for (int i = 0; i < 8; i++)
        #pragma unroll
        for (int j = 0; j < 4; j++) acc[i][j] = 0ull;

    const int ad = tid >> 1, am8 = (tid & 1) * 8;   // A: 64 d x 16 m (transpose)
    const float* Vp = v + (ad * HH + h) * N + mbase + am8;
    const int bn = tid >> 2, bmq = tid & 3;          // B: per thread 4 iters
    const float* Sb = S + h * NN + n0 * N + mbase;

    float4 ra0, ra1, rb[4];
    int rbn[4];
    // prefetch tile 0 (c0 = 0)
    ra0 = *(const float4*)(Vp);
    ra1 = *(const float4*)(Vp + 4);
    #pragma unroll
    for (int i = 0; i < 4; i++) {
        int idx = tid + i * 128;
        int nn = idx >> 2, mq = idx & 3;
        rbn[i] = nn;
        rb[i] = *(const float4*)(Sb + nn * N + mq * 4);
    }
    __syncthreads();  // rm/ri visible
    {
        As[0][am8 + 0][ad] = ra0.x; As[0][am8 + 1][ad] = ra0.y;
        As[0][am8 + 2][ad] = ra0.z; As[0][am8 + 3][ad] = ra0.w;
        As[0][am8 + 4][ad] = ra1.x; As[0][am8 + 5][ad] = ra1.y;
        As[0][am8 + 6][ad] = ra1.z; As[0][am8 + 7][ad] = ra1.w;
        #pragma unroll
        for (int i = 0; i < 4; i++) {
            int idx = tid + i * 128;
            int nn = idx >> 2, mq = idx & 3;
            float4 nm = mask_not4(mask, (n0 + nn) * N + mbase + mq * 4);
            float RM = rm[nn], RI = ri[nn];
            Bs[0][mq * 4 + 0][nn] = __expf(rb[i].x + smin * nm.x - RM) * RI;
            Bs[0][mq * 4 + 1][nn] = __expf(rb[i].y + smin * nm.y - RM) * RI;
            Bs[0][mq * 4 + 2][nn] = __expf(rb[i].z + smin * nm.z - RM) * RI;
            Bs[0][mq * 4 + 3][nn] = __expf(rb[i].w + smin * nm.w - RM) * RI;
        }
    }
    __syncthreads();

    const int KT = (N / 2) / 16;  // 64
    for (int kt = 0; kt < KT; kt++) {
        const int s = kt & 1;
        const int c1 = (kt + 1) * 16;
        if (kt + 1 < KT) {
            ra0 = *(const float4*)(Vp + c1);
            ra1 = *(const float4*)(Vp + c1 + 4);
            #pragma unroll
            for (int i = 0; i < 4; i++) {
                int idx = tid + i * 128;
                int nn = idx >> 2, mq = idx & 3;
                rb[i] = *(const float4*)(Sb + nn * N + c1 + mq * 4);
            }
        }
        gemm16(As[s], Bs[s], acc, tx, ty);
        if (kt + 1 < KT) {
            const int d = s ^ 1;
            As[d][am8 + 0][ad] = ra0.x; As[d][am8 + 1][ad] = ra0.y;
            As[d][am8 + 2][ad] = ra0.z; As[d][am8 + 3][ad] = ra0.w;
            As[d][am8 + 4][ad] = ra1.x; As[d][am8 + 5][ad] = ra1.y;
            As[d][am8 + 6][ad] = ra1.z; As[d][am8 + 7][ad] = ra1.w;
            #pragma unroll
            for (int i = 0; i < 4; i++) {
                int idx = tid + i * 128;
                int nn = idx >> 2, mq = idx & 3;
                float4 nm = mask_not4(mask, (n0 + nn) * N + mbase + c1 + mq * 4);
                float RM = rm[nn], RI = ri[nn];
                Bs[d][mq * 4 + 0][nn] = __expf(rb[i].x + smin * nm.x - RM) * RI;
                Bs[d][mq * 4 + 1][nn] = __expf(rb[i].y + smin * nm.y - RM) * RI;
                Bs[d][mq * 4 + 2][nn] = __expf(rb[i].z + smin * nm.z - RM) * RI;
                Bs[d][mq * 4 + 3][nn] = __expf(rb[i].w + smin * nm.w - RM) * RI;
            }
        }
        __syncthreads();
    }

    #pragma unroll
    for (int i = 0; i < 8; i++) {
        float2 v0 = up2(acc[i][0]), v1 = up2(acc[i][1]);
        float2 v2 = up2(acc[i][2]), v3 = up2(acc[i][3]);
        float4 o0 = {v0.x, v0.y, v1.x, v1.y};
        float4 o1 = {v2.x, v2.y, v3.x, v3.y};
        float* row = O + ((ty * 8 + i) * HH + h) * N + n0;
        *(float4*)(row + tx * 4) = o0;
        *(float4*)(row + 64 + tx * 4) = o1;
    }
}

// Merge projection: out = Wm @ (x1 + x2) + bm
__global__ __launch_bounds__(128) void merge_kernel(
    const float* __restrict__ W, const float* __restrict__ bm,
    const float* __restrict__ X1, const float* __restrict__ X2,
    float* __restrict__ O)
{
    __shared__ float As[2][16][64];
    __shared__ float Bs[2][16][132];
    const int tid = threadIdx.x, tx = tid & 15, ty = tid >> 4;
    const int n0 = blockIdx.x * 128, m0 = blockIdx.y * 64;

    ull acc[8][4];
    #pragma unroll
    for (int i = 0; i < 8; i++)
        #pragma unroll
        for (int j = 0; j < 4; j++) acc[i][j] = 0ull;

    const int ao = tid >> 1, ac = (tid & 1) * 8;
    const float* Ap = W + (m0 + ao) * DM + ac;
    const int brow = tid >> 5, bc4 = tid & 31;
    const float* B1 = X1 + brow * N + n0 + bc4 * 4;
    const float* B2 = X2 + brow * N + n0 + bc4 * 4;

    float4 ra0, ra1, rb[4];
    ra0 = *(const float4*)(Ap);
    ra1 = *(const float4*)(Ap + 4);
    #pragma unroll
    for (int i = 0; i < 4; i++) {
        float4 a = *(const float4*)(B1 + (i * 4) * N);
        float4 b = *(const float4*)(B2 + (i * 4) * N);
        rb[i] = make_float4(a.x + b.x, a.y + b.y, a.z + b.z, a.w + b.w);
    }
    {
        As[0][ac + 0][ao] = ra0.x; As[0][ac + 1][ao] = ra0.y;
        As[0][ac + 2][ao] = ra0.z; As[0][ac + 3][ao] = ra0.w;
        As[0][ac + 4][ao] = ra1.x; As[0][ac + 5][ao] = ra1.y;
        As[0][ac + 6][ao] = ra1.z; As[0][ac + 7][ao] = ra1.w;
        #pragma unroll
        for (int i = 0; i < 4; i++)
            *(float4*)&Bs[0][brow + i * 4][bc4 * 4] = rb[i];
    }
    __syncthreads();

    const int KT = DM / 16;
    for (int kt = 0; kt < KT; kt++) {
        const int s = kt & 1;
        if (kt + 1 < KT) {
            const int c0 = (kt + 1) * 16;
            ra0 = *(const float4*)(Ap + c0);
            ra1 = *(const float4*)(Ap + c0 + 4);
            #pragma unroll
            for (int i = 0; i < 4; i++) {
                float4 a = *(const float4*)(B1 + (c0 + i * 4) * N);
                float4 b = *(const float4*)(B2 + (c0 + i * 4) * N);
                rb[i] = make_float4(a.x + b.x, a.y + b.y, a.z + b.z, a.w + b.w);
            }
        }
        gemm16(As[s], Bs[s], acc, tx, ty);
        if (kt + 1 < KT) {
            const int d = s ^ 1;
            As[d][ac + 0][ao] = ra0.x; As[d][ac + 1][ao] = ra0.y;
            As[d][ac + 2][ao] = ra0.z; As[d][ac + 3][ao] = ra0.w;
            As[d][ac + 4][ao] = ra1.x; As[d][ac + 5][ao] = ra1.y;
            As[d][ac + 6][ao] = ra1.z; As[d][ac + 7][ao] = ra1.w;
            #pragma unroll
            for (int i = 0; i < 4; i++)
                *(float4*)&Bs[d][brow + i * 4][bc4 * 4] = rb[i];
        }
        __syncthreads();
    }

    #pragma unroll
    for (int i = 0; i < 8; i++) {
        float bias = bm[m0 + ty * 8 + i];
        float2 v0 = up2(acc[i][0]), v1 = up2(acc[i][1]);
        float2 v2 = up2(acc[i][2]), v3 = up2(acc[i][3]);
        float4 o0 = {v0.x + bias, v0.y + bias, v1.x + bias, v1.y + bias};
        float4 o1 = {v2.x + bias, v2.y + bias, v3.x + bias, v3.y + bias};
        float* row = O + (m0 + ty * 8 + i) * N + n0;
        *(float4*)(row + tx * 4) = o0;
        *(float4*)(row + 64 + tx * 4) = o1;
    }
}

// ---------------- launch ----------------
extern "C" void kernel_launch(void* const* d_in, const int* in_sizes, int n_in,
                              void* d_out, int out_size) {
    const float* query = (const float*)d_in[0];
    const float* key   = (const float*)d_in[1];
    const float* value = (const float*)d_in[2];
    const void*  mask  = d_in[4];
    const float* Wq = (const float*)d_in[5];
    const float* bq = (const float*)d_in[6];
    const float* Wk = (const float*)d_in[7];
    const float* bk = (const float*)d_in[8];
    const float* Wv = (const float*)d_in[9];
    const float* bv = (const float*)d_in[10];
    const float* Wm = (const float*)d_in[11];
    const float* bm = (const float*)d_in[12];
    float* out = (float*)d_out;

    float *qp, *kp, *vp, *x1p, *x2p, *Sp;
    cudaGetSymbolAddress((void**)&qp, g_q);
    cudaGetSymbolAddress((void**)&kp, g_k);
    cudaGetSymbolAddress((void**)&vp, g_v);
    cudaGetSymbolAddress((void**)&x1p, g_x1);
    cudaGetSymbolAddress((void**)&x2p, g_x2);
    cudaGetSymbolAddress((void**)&Sp, g_S);

    init_kernel<<<1, 1>>>();
    mask_detect_kernel<<<128, 256>>>((const unsigned*)mask);

    qkv_kernel<<<dim3(N / 128, DM / 64, 3), 128>>>(
        Wq, Wk, Wv, bq, bk, bv, query, key, value, qp, kp, vp);

    scores_kernel<<<dim3(N / 128, N / 64, HH), 128>>>(qp, kp, Sp);

    stats_kernel<<<N, 256>>>(Sp, mask, out + DM * N);

    pv_kernel<<<dim3(N / 128, 2, HH), 128>>>(Sp, vp, mask, x1p, x2p);

    merge_kernel<<<dim3(N / 128, DM / 64), 128>>>(Wm, bm, x1p, x2p, out);
}

// round 5
// speedup vs baseline: 1.8976x; 1.1260x over previous
#include <cuda_runtime.h>

#define N      2048
#define DM     512
#define HH     8
#define NN     (N * N)

typedef unsigned long long ull;

// ---------------- device scratch ----------------
__device__ float    g_q[DM * N];
__device__ float    g_k[DM * N];
__device__ float    g_v[DM * N];
__device__ float    g_x1[DM * N];
__device__ float    g_x2[DM * N];
__device__ float    g_S[HH * NN];      // raw scores
__device__ float    g_E[HH * NN];      // exp(raw scores)
__device__ float    g_psu[HH * N * 16]; // per-(h,n,mtile) unmasked exp sum
__device__ float    g_psm[HH * N * 16]; // masked exp sum
__device__ float    g_rinv[HH * N];
__device__ unsigned g_smin_enc;
__device__ unsigned g_mask_or;

// ---------------- helpers ----------------
__device__ __forceinline__ unsigned enc_f(float x) {
    unsigned u = __float_as_uint(x);
    return (u & 0x80000000u) ? ~u : (u | 0x80000000u);
}
__device__ __forceinline__ float dec_f(unsigned u) {
    return (u & 0x80000000u) ? __uint_as_float(u & 0x7FFFFFFFu)
                             : __uint_as_float(~u);
}
__device__ __forceinline__ float mask_not(const void* mask, int i, unsigned o) {
    bool mv;
    if (o == 0x3F800000u)      mv = ((const float*)mask)[i] != 0.0f;
    else if (o == 1u)          mv = ((const int*)mask)[i] != 0;
    else                       mv = ((const unsigned char*)mask)[i] != 0;
    return mv ? 0.0f : 1.0f;
}
__device__ __forceinline__ float4 mask_not4(const void* mask, int i, unsigned o) {
    float4 r;
    if (o == 0x3F800000u) {
        float4 m = *(const float4*)((const float*)mask + i);
        r.x = m.x != 0.0f ? 0.f : 1.f; r.y = m.y != 0.0f ? 0.f : 1.f;
        r.z = m.z != 0.0f ? 0.f : 1.f; r.w = m.w != 0.0f ? 0.f : 1.f;
    } else if (o == 1u) {
        int4 m = *(const int4*)((const int*)mask + i);
        r.x = m.x ? 0.f : 1.f; r.y = m.y ? 0.f : 1.f;
        r.z = m.z ? 0.f : 1.f; r.w = m.w ? 0.f : 1.f;
    } else {
        uchar4 m = *(const uchar4*)((const unsigned char*)mask + i);
        r.x = m.x ? 0.f : 1.f; r.y = m.y ? 0.f : 1.f;
        r.z = m.z ? 0.f : 1.f; r.w = m.w ? 0.f : 1.f;
    }
    return r;
}

__device__ __forceinline__ void ffma2(ull& d, ull a, ull b) {
    asm("fma.rn.f32x2 %0, %1, %2, %0;" : "+l"(d) : "l"(a), "l"(b));
}
__device__ __forceinline__ ull pk2(float x, float y) {
    ull r; asm("mov.b64 %0, {%1, %2};" : "=l"(r) : "f"(x), "f"(y)); return r;
}
__device__ __forceinline__ float2 up2(ull p) {
    float2 r; asm("mov.b64 {%0, %1}, %2;" : "=f"(r.x), "=f"(r.y) : "l"(p)); return r;
}

// 16-deep K-slab of a 64(M)x128(N) tile: 128 threads, 8x8 per thread.
__device__ __forceinline__ void gemm16(const float (*__restrict__ As)[64],
                                       const float (*__restrict__ Bs)[132],
                                       ull acc[8][4], int tx, int ty) {
    #pragma unroll
    for (int k = 0; k < 16; k++) {
        float4 a0 = *(const float4*)&As[k][ty * 8];
        float4 a1 = *(const float4*)&As[k][ty * 8 + 4];
        float4 b0 = *(const float4*)&Bs[k][tx * 4];
        float4 b1 = *(const float4*)&Bs[k][64 + tx * 4];
        ull pb0 = pk2(b0.x, b0.y), pb1 = pk2(b0.z, b0.w);
        ull pb2 = pk2(b1.x, b1.y), pb3 = pk2(b1.z, b1.w);
        float av[8] = {a0.x, a0.y, a0.z, a0.w, a1.x, a1.y, a1.z, a1.w};
        #pragma unroll
        for (int i = 0; i < 8; i++) {
            ull pa = pk2(av[i], av[i]);
            ffma2(acc[i][0], pa, pb0);
            ffma2(acc[i][1], pa, pb1);
            ffma2(acc[i][2], pa, pb2);
            ffma2(acc[i][3], pa, pb3);
        }
    }
}

// ---------------- kernels ----------------

__global__ void init_kernel() {
    g_smin_enc = 0xFFFFFFFFu;
    g_mask_or  = 0u;
}

__global__ void mask_detect_kernel(const unsigned* __restrict__ m) {
    __shared__ unsigned sh[256];
    unsigned acc = 0;
    const int total = NN / 4;
    for (int i = blockIdx.x * blockDim.x + threadIdx.x; i < total;
         i += gridDim.x * blockDim.x)
        acc |= m[i];
    sh[threadIdx.x] = acc;
    __syncthreads();
    for (int s = 128; s > 0; s >>= 1) {
        if (threadIdx.x < s) sh[threadIdx.x] |= sh[threadIdx.x + s];
        __syncthreads();
    }
    if (threadIdx.x == 0) atomicOr(&g_mask_or, sh[0]);
}

// Fused q/k/v projections.
__global__ __launch_bounds__(128) void qkv_kernel(
    const float* __restrict__ Wq, const float* __restrict__ Wk,
    const float* __restrict__ Wv, const float* __restrict__ bq,
    const float* __restrict__ bk, const float* __restrict__ bv,
    const float* __restrict__ Xq, const float* __restrict__ Xk,
    const float* __restrict__ Xv,
    float* __restrict__ Oq, float* __restrict__ Ok, float* __restrict__ Ov)
{
    const float *W, *Bv_, *X;
    float* O;
    if (blockIdx.z == 0)      { W = Wq; Bv_ = bq; X = Xq; O = Oq; }
    else if (blockIdx.z == 1) { W = Wk; Bv_ = bk; X = Xk; O = Ok; }
    else                      { W = Wv; Bv_ = bv; X = Xv; O = Ov; }

    __shared__ float As[2][16][64];
    __shared__ float Bs[2][16][132];
    const int tid = threadIdx.x, tx = tid & 15, ty = tid >> 4;
    const int n0 = blockIdx.x * 128, m0 = blockIdx.y * 64;

    ull acc[8][4];
    #pragma unroll
    for (int i = 0; i < 8; i++)
        #pragma unroll
        for (int j = 0; j < 4; j++) acc[i][j] = 0ull;

    const int ao = tid >> 1, ac = (tid & 1) * 8;
    const float* Ap = W + (m0 + ao) * DM + ac;
    const int brow = tid >> 5, bc4 = tid & 31;
    const float* Bp = X + brow * N + n0 + bc4 * 4;

    float4 ra0, ra1, rb[4];
    ra0 = *(const float4*)(Ap);
    ra1 = *(const float4*)(Ap + 4);
    #pragma unroll
    for (int i = 0; i < 4; i++)
        rb[i] = *(const float4*)(Bp + (i * 4) * N);
    {
        As[0][ac + 0][ao] = ra0.x; As[0][ac + 1][ao] = ra0.y;
        As[0][ac + 2][ao] = ra0.z; As[0][ac + 3][ao] = ra0.w;
        As[0][ac + 4][ao] = ra1.x; As[0][ac + 5][ao] = ra1.y;
        As[0][ac + 6][ao] = ra1.z; As[0][ac + 7][ao] = ra1.w;
        #pragma unroll
        for (int i = 0; i < 4; i++)
            *(float4*)&Bs[0][brow + i * 4][bc4 * 4] = rb[i];
    }
    __syncthreads();

    const int KT = DM / 16;
    for (int kt = 0; kt < KT; kt++) {
        const int s = kt & 1;
        if (kt + 1 < KT) {
            const int c0 = (kt + 1) * 16;
            ra0 = *(const float4*)(Ap + c0);
            ra1 = *(const float4*)(Ap + c0 + 4);
            #pragma unroll
            for (int i = 0; i < 4; i++)
                rb[i] = *(const float4*)(Bp + (c0 + i * 4) * N);
        }
        gemm16(As[s], Bs[s], acc, tx, ty);
        if (kt + 1 < KT) {
            const int d = s ^ 1;
            As[d][ac + 0][ao] = ra0.x; As[d][ac + 1][ao] = ra0.y;
            As[d][ac + 2][ao] = ra0.z; As[d][ac + 3][ao] = ra0.w;
            As[d][ac + 4][ao] = ra1.x; As[d][ac + 5][ao] = ra1.y;
            As[d][ac + 6][ao] = ra1.z; As[d][ac + 7][ao] = ra1.w;
            #pragma unroll
            for (int i = 0; i < 4; i++)
                *(float4*)&Bs[d][brow + i * 4][bc4 * 4] = rb[i];
        }
        __syncthreads();
    }

    #pragma unroll
    for (int i = 0; i < 8; i++) {
        float bias = Bv_[m0 + ty * 8 + i];
        float2 v0 = up2(acc[i][0]), v1 = up2(acc[i][1]);
        float2 v2 = up2(acc[i][2]), v3 = up2(acc[i][3]);
        float4 o0 = {v0.x + bias, v0.y + bias, v1.x + bias, v1.y + bias};
        float4 o1 = {v2.x + bias, v2.y + bias, v3.x + bias, v3.y + bias};
        float* row = O + (m0 + ty * 8 + i) * N + n0;
        *(float4*)(row + tx * 4) = o0;
        *(float4*)(row + 64 + tx * 4) = o1;
    }
}

// Scores tile [n=64][m=128]: stores S and E=exp(S), per-row masked/unmasked
// exp partial sums, and global raw-score min.
__global__ __launch_bounds__(128) void scores_kernel(
    const float* __restrict__ q, const float* __restrict__ k,
    const void* __restrict__ mask,
    float* __restrict__ S, float* __restrict__ E)
{
    __shared__ float As[2][16][64];
    __shared__ float Bs[2][16][132];
    __shared__ float red[4];
    const int tid = threadIdx.x, tx = tid & 15, ty = tid >> 4;
    const int m0 = blockIdx.x * 128, n0 = blockIdx.y * 64;
    const int h = blockIdx.z;

    ull acc[8][4];
    #pragma unroll
    for (int i = 0; i < 8; i++)
        #pragma unroll
        for (int j = 0; j < 4; j++) acc[i][j] = 0ull;

    const int ad = tid >> 3, anq = tid & 7;
    const float* Ap = q + (ad * HH + h) * N + n0 + anq * 8;
    const int brow = tid >> 5, bc4 = tid & 31;
    const float* Bp = k + (brow * HH + h) * N + m0 + bc4 * 4;
    const int dstep = 16 * HH * N;

    float4 ra0, ra1, rb[4];
    ra0 = *(const float4*)(Ap);
    ra1 = *(const float4*)(Ap + 4);
    #pragma unroll
    for (int i = 0; i < 4; i++)
        rb[i] = *(const float4*)(Bp + i * 4 * HH * N);
    {
        *(float4*)&As[0][ad][anq * 8] = ra0;
        *(float4*)&As[0][ad][anq * 8 + 4] = ra1;
        #pragma unroll
        for (int i = 0; i < 4; i++)
            *(float4*)&Bs[0][brow + i * 4][bc4 * 4] = rb[i];
    }
    __syncthreads();

    const int KT = 4;
    for (int kt = 0; kt < KT; kt++) {
        const int s = kt & 1;
        if (kt + 1 < KT) {
            const int off = (kt + 1) * dstep;
            ra0 = *(const float4*)(Ap + off);
            ra1 = *(const float4*)(Ap + off + 4);
            #pragma unroll
            for (int i = 0; i < 4; i++)
                rb[i] = *(const float4*)(Bp + off + i * 4 * HH * N);
        }
        gemm16(As[s], Bs[s], acc, tx, ty);
        if (kt + 1 < KT) {
            const int d = s ^ 1;
            *(float4*)&As[d][ad][anq * 8] = ra0;
            *(float4*)&As[d][ad][anq * 8 + 4] = ra1;
            #pragma unroll
            for (int i = 0; i < 4; i++)
                *(float4*)&Bs[d][brow + i * 4][bc4 * 4] = rb[i];
        }
        __syncthreads();
    }

    const unsigned mo = g_mask_or;
    float lmin = 3.0e38f;
    float* Sb = S + h * NN;
    float* Eb = E + h * NN;
    float su[8], sm[8];
    #pragma unroll
    for (int i = 0; i < 8; i++) {
        const int row = n0 + ty * 8 + i;
        float2 v0 = up2(acc[i][0]), v1 = up2(acc[i][1]);
        float2 v2 = up2(acc[i][2]), v3 = up2(acc[i][3]);
        float4 o0 = {v0.x * 0.125f, v0.y * 0.125f, v1.x * 0.125f, v1.y * 0.125f};
        float4 o1 = {v2.x * 0.125f, v2.y * 0.125f, v3.x * 0.125f, v3.y * 0.125f};
        float* srow = Sb + row * N + m0;
        *(float4*)(srow + tx * 4) = o0;
        *(float4*)(srow + 64 + tx * 4) = o1;
        lmin = fminf(lmin, fminf(fminf(o0.x, o0.y), fminf(o0.z, o0.w)));
        lmin = fminf(lmin, fminf(fminf(o1.x, o1.y), fminf(o1.z, o1.w)));
        float4 e0 = {__expf(o0.x), __expf(o0.y), __expf(o0.z), __expf(o0.w)};
        float4 e1 = {__expf(o1.x), __expf(o1.y), __expf(o1.z), __expf(o1.w)};
        float* erow = Eb + row * N + m0;
        *(float4*)(erow + tx * 4) = e0;
        *(float4*)(erow + 64 + tx * 4) = e1;
        float4 nm0 = mask_not4(mask, row * N + m0 + tx * 4, mo);
        float4 nm1 = mask_not4(mask, row * N + m0 + 64 + tx * 4, mo);
        float tm = e0.x * nm0.x + e0.y * nm0.y + e0.z * nm0.z + e0.w * nm0.w
                 + e1.x * nm1.x + e1.y * nm1.y + e1.z * nm1.z + e1.w * nm1.w;
        float tt = e0.x + e0.y + e0.z + e0.w + e1.x + e1.y + e1.z + e1.w;
        sm[i] = tm;
        su[i] = tt - tm;
    }
    // reduce su/sm over the 16 tx lanes (same ty)
    #pragma unroll
    for (int o = 8; o > 0; o >>= 1)
        #pragma unroll
        for (int i = 0; i < 8; i++) {
            su[i] += __shfl_xor_sync(~0u, su[i], o);
            sm[i] += __shfl_xor_sync(~0u, sm[i], o);
        }
    if (tx == 0) {
        #pragma unroll
        for (int i = 0; i < 8; i++) {
            const int row = n0 + ty * 8 + i;
            g_psu[(h * N + row) * 16 + blockIdx.x] = su[i];
            g_psm[(h * N + row) * 16 + blockIdx.x] = sm[i];
        }
    }
    #pragma unroll
    for (int o = 16; o > 0; o >>= 1)
        lmin = fminf(lmin, __shfl_xor_sync(~0u, lmin, o));
    if ((tid & 31) == 0) red[tid >> 5] = lmin;
    __syncthreads();
    if (tid == 0) {
        float m = fminf(fminf(red[0], red[1]), fminf(red[2], red[3]));
        atomicMin(&g_smin_enc, enc_f(m));
    }
}

// rinv[h][n] = 1 / (sum_unmasked + exp(smin) * sum_masked)
__global__ void rinv_kernel() {
    int idx = blockIdx.x * 256 + threadIdx.x;   // h*N+n
    float es = __expf(dec_f(g_smin_enc));
    float a = 0.f, b = 0.f;
    #pragma unroll
    for (int t = 0; t < 16; t++) {
        a += g_psu[idx * 16 + t];
        b += g_psm[idx * 16 + t];
    }
    g_rinv[idx] = 1.0f / (a + es * b);
}

// out2[n][m] = mean_h(S) + smin * notm
__global__ __launch_bounds__(256) void mean_kernel(
    const float* __restrict__ S, const void* __restrict__ mask,
    float* __restrict__ out2)
{
    int idx = blockIdx.x * 256 + threadIdx.x;
    const unsigned mo = g_mask_or;
    float smin = dec_f(g_smin_enc);
    float s = 0.0f;
    #pragma unroll
    for (int h = 0; h < HH; h++) s += S[h * NN + idx];
    out2[idx] = s * 0.125f + smin * mask_not(mask, idx, mo);
}

// PV: x[(d*8+h)][n] = sum_m P v, P = E*(1+notm*(es-1))*rinv[n]. No exp.
__global__ __launch_bounds__(128) void pv_kernel(
    const float* __restrict__ E, const float* __restrict__ v,
    const void* __restrict__ mask,
    float* __restrict__ X1, float* __restrict__ X2)
{
    __shared__ float As[2][16][64];
    __shared__ float Bs[2][16][132];
    __shared__ float ri[128];
    const int tid = threadIdx.x, tx = tid & 15, ty = tid >> 4;
    const int n0 = blockIdx.x * 128;
    const int mbase = blockIdx.y * (N / 2);
    const int h = blockIdx.z;
    float* O = blockIdx.y ? X2 : X1;

    ri[tid] = g_rinv[h * N + n0 + tid];
    const unsigned mo = g_mask_or;
    const float esm1 = __expf(dec_f(g_smin_enc)) - 1.0f;

    ull acc[8][4];
    #pragma unroll
    for (int i = 0; i < 8; i++)
        #pragma unroll
        for (int j = 0; j < 4; j++) acc[i][j] = 0ull;

    const int ad = tid >> 1, am8 = (tid & 1) * 8;
    const float* Vp = v + (ad * HH + h) * N + mbase + am8;
    const float* Sb = E + h * NN + n0 * N + mbase;

    float4 ra0, ra1, rb[4];
    ra0 = *(const float4*)(Vp);
    ra1 = *(const float4*)(Vp + 4);
    #pragma unroll
    for (int i = 0; i < 4; i++) {
        int idx = tid + i * 128;
        int nn = idx >> 2, mq = idx & 3;
        rb[i] = *(const float4*)(Sb + nn * N + mq * 4);
    }
    __syncthreads();
    {
        As[0][am8 + 0][ad] = ra0.x; As[0][am8 + 1][ad] = ra0.y;
        As[0][am8 + 2][ad] = ra0.z; As[0][am8 + 3][ad] = ra0.w;
        As[0][am8 + 4][ad] = ra1.x; As[0][am8 + 5][ad] = ra1.y;
        As[0][am8 + 6][ad] = ra1.z; As[0][am8 + 7][ad] = ra1.w;
        #pragma unroll
        for (int i = 0; i < 4; i++) {
            int idx = tid + i * 128;
            int nn = idx >> 2, mq = idx & 3;
            float4 nm = mask_not4(mask, (n0 + nn) * N + mbase + mq * 4, mo);
            float RI = ri[nn];
            Bs[0][mq * 4 + 0][nn] = rb[i].x * fmaf(nm.x, esm1, 1.f) * RI;
            Bs[0][mq * 4 + 1][nn] = rb[i].y * fmaf(nm.y, esm1, 1.f) * RI;
            Bs[0][mq * 4 + 2][nn] = rb[i].z * fmaf(nm.z, esm1, 1.f) * RI;
            Bs[0][mq * 4 + 3][nn] = rb[i].w * fmaf(nm.w, esm1, 1.f) * RI;
        }
    }
    __syncthreads();

    const int KT = (N / 2) / 16;
    for (int kt = 0; kt < KT; kt++) {
        const int s = kt & 1;
        const int c1 = (kt + 1) * 16;
        if (kt + 1 < KT) {
            ra0 = *(const float4*)(Vp + c1);
            ra1 = *(const float4*)(Vp + c1 + 4);
            #pragma unroll
            for (int i = 0; i < 4; i++) {
                int idx = tid + i * 128;
                int nn = idx >> 2, mq = idx & 3;
                rb[i] = *(const float4*)(Sb + nn * N + c1 + mq * 4);
            }
        }
        gemm16(As[s], Bs[s], acc, tx, ty);
        if (kt + 1 < KT) {
            const int d = s ^ 1;
            As[d][am8 + 0][ad] = ra0.x; As[d][am8 + 1][ad] = ra0.y;
            As[d][am8 + 2][ad] = ra0.z; As[d][am8 + 3][ad] = ra0.w;
            As[d][am8 + 4][ad] = ra1.x; As[d][am8 + 5][ad] = ra1.y;
            As[d][am8 + 6][ad] = ra1.z; As[d][am8 + 7][ad] = ra1.w;
            #pragma unroll
            for (int i = 0; i < 4; i++) {
                int idx = tid + i * 128;
                int nn = idx >> 2, mq = idx & 3;
                float4 nm = mask_not4(mask, (n0 + nn) * N + mbase + c1 + mq * 4, mo);
                float RI = ri[nn];
                Bs[d][mq * 4 + 0][nn] = rb[i].x * fmaf(nm.x, esm1, 1.f) * RI;
                Bs[d][mq * 4 + 1][nn] = rb[i].y * fmaf(nm.y, esm1, 1.f) * RI;
                Bs[d][mq * 4 + 2][nn] = rb[i].z * fmaf(nm.z, esm1, 1.f) * RI;
                Bs[d][mq * 4 + 3][nn] = rb[i].w * fmaf(nm.w, esm1, 1.f) * RI;
            }
        }
        __syncthreads();
    }

    #pragma unroll
    for (int i = 0; i < 8; i++) {
        float2 v0 = up2(acc[i][0]), v1 = up2(acc[i][1]);
        float2 v2 = up2(acc[i][2]), v3 = up2(acc[i][3]);
        float4 o0 = {v0.x, v0.y, v1.x, v1.y};
        float4 o1 = {v2.x, v2.y, v3.x, v3.y};
        float* row = O + ((ty * 8 + i) * HH + h) * N + n0;
        *(float4*)(row + tx * 4) = o0;
        *(float4*)(row + 64 + tx * 4) = o1;
    }
}

// Merge projection: out = Wm @ (x1 + x2) + bm
__global__ __launch_bounds__(128) void merge_kernel(
    const float* __restrict__ W, const float* __restrict__ bm,
    const float* __restrict__ X1, const float* __restrict__ X2,
    float* __restrict__ O)
{
    __shared__ float As[2][16][64];
    __shared__ float Bs[2][16][132];
    const int tid = threadIdx.x, tx = tid & 15, ty = tid >> 4;
    const int n0 = blockIdx.x * 128, m0 = blockIdx.y * 64;

    ull acc[8][4];
    #pragma unroll
    for (int i = 0; i < 8; i++)
        #pragma unroll
        for (int j = 0; j < 4; j++) acc[i][j] = 0ull;

    const int ao = tid >> 1, ac = (tid & 1) * 8;
    const float* Ap = W + (m0 + ao) * DM + ac;
    const int brow = tid >> 5, bc4 = tid & 31;
    const float* B1 = X1 + brow * N + n0 + bc4 * 4;
    const float* B2 = X2 + brow * N + n0 + bc4 * 4;

    float4 ra0, ra1, rb[4];
    ra0 = *(const float4*)(Ap);
    ra1 = *(const float4*)(Ap + 4);
    #pragma unroll
    for (int i = 0; i < 4; i++) {
        float4 a = *(const float4*)(B1 + (i * 4) * N);
        float4 b = *(const float4*)(B2 + (i * 4) * N);
        rb[i] = make_float4(a.x + b.x, a.y + b.y, a.z + b.z, a.w + b.w);
    }
    {
        As[0][ac + 0][ao] = ra0.x; As[0][ac + 1][ao] = ra0.y;
        As[0][ac + 2][ao] = ra0.z; As[0][ac + 3][ao] = ra0.w;
        As[0][ac + 4][ao] = ra1.x; As[0][ac + 5][ao] = ra1.y;
        As[0][ac + 6][ao] = ra1.z; As[0][ac + 7][ao] = ra1.w;
        #pragma unroll
        for (int i = 0; i < 4; i++)
            *(float4*)&Bs[0][brow + i * 4][bc4 * 4] = rb[i];
    }
    __syncthreads();

    const int KT = DM / 16;
    for (int kt = 0; kt < KT; kt++) {
        const int s = kt & 1;
        if (kt + 1 < KT) {
            const int c0 = (kt + 1) * 16;
            ra0 = *(const float4*)(Ap + c0);
            ra1 = *(const float4*)(Ap + c0 + 4);
            #pragma unroll
            for (int i = 0; i < 4; i++) {
                float4 a = *(const float4*)(B1 + (c0 + i * 4) * N);
                float4 b = *(const float4*)(B2 + (c0 + i * 4) * N);
                rb[i] = make_float4(a.x + b.x, a.y + b.y, a.z + b.z, a.w + b.w);
            }
        }
        gemm16(As[s], Bs[s], acc, tx, ty);
        if (kt + 1 < KT) {
            const int d = s ^ 1;
            As[d][ac + 0][ao] = ra0.x; As[d][ac + 1][ao] = ra0.y;
            As[d][ac + 2][ao] = ra0.z; As[d][ac + 3][ao] = ra0.w;
            As[d][ac + 4][ao] = ra1.x; As[d][ac + 5][ao] = ra1.y;
            As[d][ac + 6][ao] = ra1.z; As[d][ac + 7][ao] = ra1.w;
            #pragma unroll
            for (int i = 0; i < 4; i++)
                *(float4*)&Bs[d][brow + i * 4][bc4 * 4] = rb[i];
        }
        __syncthreads();
    }

    #pragma unroll
    for (int i = 0; i < 8; i++) {
        float bias = bm[m0 + ty * 8 + i];
        float2 v0 = up2(acc[i][0]), v1 = up2(acc[i][1]);
        float2 v2 = up2(acc[i][2]), v3 = up2(acc[i][3]);
        float4 o0 = {v0.x + bias, v0.y + bias, v1.x + bias, v1.y + bias};
        float4 o1 = {v2.x + bias, v2.y + bias, v3.x + bias, v3.y + bias};
        float* row = O + (m0 + ty * 8 + i) * N + n0;
        *(float4*)(row + tx * 4) = o0;
        *(float4*)(row + 64 + tx * 4) = o1;
    }
}

// ---------------- launch ----------------
extern "C" void kernel_launch(void* const* d_in, const int* in_sizes, int n_in,
                              void* d_out, int out_size) {
    const float* query = (const float*)d_in[0];
    const float* key   = (const float*)d_in[1];
    const float* value = (const float*)d_in[2];
    const void*  mask  = d_in[4];
    const float* Wq = (const float*)d_in[5];
    const float* bq = (const float*)d_in[6];
    const float* Wk = (const float*)d_in[7];
    const float* bk = (const float*)d_in[8];
    const float* Wv = (const float*)d_in[9];
    const float* bv = (const float*)d_in[10];
    const float* Wm = (const float*)d_in[11];
    const float* bm = (const float*)d_in[12];
    float* out = (float*)d_out;

    float *qp, *kp, *vp, *x1p, *x2p, *Sp, *Ep;
    cudaGetSymbolAddress((void**)&qp, g_q);
    cudaGetSymbolAddress((void**)&kp, g_k);
    cudaGetSymbolAddress((void**)&vp, g_v);
    cudaGetSymbolAddress((void**)&x1p, g_x1);
    cudaGetSymbolAddress((void**)&x2p, g_x2);
    cudaGetSymbolAddress((void**)&Sp, g_S);
    cudaGetSymbolAddress((void**)&Ep, g_E);

    init_kernel<<<1, 1>>>();
    mask_detect_kernel<<<128, 256>>>((const unsigned*)mask);

    qkv_kernel<<<dim3(N / 128, DM / 64, 3), 128>>>(
        Wq, Wk, Wv, bq, bk, bv, query, key, value, qp, kp, vp);

    scores_kernel<<<dim3(N / 128, N / 64, HH), 128>>>(qp, kp, mask, Sp, Ep);

    rinv_kernel<<<HH * N / 256, 256>>>();
    mean_kernel<<<NN / 256, 256>>>(Sp, mask, out + DM * N);

    pv_kernel<<<dim3(N / 128, 2, HH), 128>>>(Ep, vp, mask, x1p, x2p);

    merge_kernel<<<dim3(N / 128, DM / 64), 128>>>(Wm, bm, x1p, x2p, out);
}